// round 12
// baseline (speedup 1.0000x reference)
#include <cuda_runtime.h>
#include <cuda_bf16.h>
#include <math.h>
#include <stdint.h>

// Problem constants
constexpr int NN  = 16384;   // nodes
constexpr int DD  = 128;     // dim
constexpr int EE  = 262144;  // edges
constexpr int SEQ = 512;     // nodes per graph
constexpr int NGR = 32;      // graphs
constexpr int NH  = 8;       // heads (dh = 16)

// ---------------- scratch ----------------
__device__ float g_z   [NN * DD];
__device__ float g_hl  [NN * DD];
__device__ float g_qkv [NN * 3 * DD];
__device__ float g_ao  [NN * DD];
__device__ float g_ha  [NN * DD];
__device__ float g_h   [NN * DD];
__device__ float g_h2  [NN * DD];
__device__ float g_stats[768];   // [0:256) hl, [256:512) ha, [512:768) h2
__device__ int   g_deg [NN];
__device__ int   g_off [NN + 1];
__device__ int   g_pos [NN];
__device__ int   g_eid [EE];

// =====================================================================
__global__ void zero_misc(int* deg, float* stats)
{
    int i = blockIdx.x * 256 + threadIdx.x;
    deg[i] = 0;
    if (i < 768) stats[i] = 0.f;
}

// =====================================================================
// CSR build by dst:  count -> scan -> scatter
// =====================================================================
__global__ void count_kernel(const int* __restrict__ dst, int* __restrict__ deg)
{
    int e = blockIdx.x * 256 + threadIdx.x;
    atomicAdd(&deg[dst[e]], 1);
}

__global__ void __launch_bounds__(1024)
scan_kernel(const int* __restrict__ deg, int* __restrict__ off, int* __restrict__ pos)
{
    __shared__ int buf[2][1024];
    int t = threadIdx.x;
    int base = t * 16;
    int loc[16];
    int sum = 0;
#pragma unroll
    for (int i = 0; i < 16; ++i) { loc[i] = sum; sum += deg[base + i]; }
    buf[0][t] = sum;
    __syncthreads();
    int sel = 0;
    for (int d = 1; d < 1024; d <<= 1) {
        int v = buf[sel][t] + (t >= d ? buf[sel][t - d] : 0);
        buf[sel ^ 1][t] = v;
        sel ^= 1;
        __syncthreads();
    }
    int excl = buf[sel][t] - sum;
#pragma unroll
    for (int i = 0; i < 16; ++i) {
        int o = excl + loc[i];
        off[base + i] = o;
        pos[base + i] = o;
    }
    if (t == 1023) off[NN] = excl + sum;
}

__global__ void scatter_kernel(const int* __restrict__ dst, int* __restrict__ pos,
                               int* __restrict__ eid)
{
    int e = blockIdx.x * 256 + threadIdx.x;
    int p = atomicAdd(&pos[dst[e]], 1);
    eid[p] = e;
}

// =====================================================================
// Gather aggregation: z = x + sum_{e -> node} relu(x[src[e]] + ea[e])
// =====================================================================
__global__ void __launch_bounds__(256)
aggr_kernel(const float* __restrict__ x, const int* __restrict__ src,
            const float* __restrict__ ea, const int* __restrict__ off,
            const int* __restrict__ eid, float* __restrict__ z)
{
    int node = blockIdx.x * 8 + (threadIdx.x >> 5);
    int lane = threadIdx.x & 31;
    int beg = off[node], end = off[node + 1];
    const float4* x4  = (const float4*)x;
    const float4* ea4 = (const float4*)ea;
    float4 acc = make_float4(0.f, 0.f, 0.f, 0.f);
#pragma unroll 2
    for (int i = beg; i < end; ++i) {
        int e = __ldg(eid + i);
        int s = __ldg(src + e);
        float4 a = x4[(size_t)s * 32 + lane];
        float4 b = ea4[(size_t)e * 32 + lane];
        acc.x += fmaxf(a.x + b.x, 0.f);
        acc.y += fmaxf(a.y + b.y, 0.f);
        acc.z += fmaxf(a.z + b.z, 0.f);
        acc.w += fmaxf(a.w + b.w, 0.f);
    }
    float4 xv = x4[(size_t)node * 32 + lane];
    ((float4*)z)[(size_t)node * 32 + lane] =
        make_float4(xv.x + acc.x, xv.y + acc.y, xv.z + acc.z, xv.w + acc.w);
}

// =====================================================================
// mma helpers
// =====================================================================
__device__ __forceinline__ uint32_t to_tf32(float f)
{
    uint32_t u;
    asm("cvt.rna.tf32.f32 %0, %1;" : "=r"(u) : "f"(f));
    return u;
}

__device__ __forceinline__ void mma_tf32(float c[4], const uint32_t a[4], const uint32_t b[2])
{
    asm volatile(
        "mma.sync.aligned.m16n8k8.row.col.f32.tf32.tf32.f32 "
        "{%0,%1,%2,%3}, {%4,%5,%6,%7}, {%8,%9}, {%0,%1,%2,%3};\n"
        : "+f"(c[0]), "+f"(c[1]), "+f"(c[2]), "+f"(c[3])
        : "r"(a[0]), "r"(a[1]), "r"(a[2]), "r"(a[3]), "r"(b[0]), "r"(b[1]));
}

// bf16 m16n8k16 mma, f32 accumulate
__device__ __forceinline__ void mma_bf16(float c[4], const uint32_t a[4], const uint32_t b[2])
{
    asm volatile(
        "mma.sync.aligned.m16n8k16.row.col.f32.bf16.bf16.f32 "
        "{%0,%1,%2,%3}, {%4,%5,%6,%7}, {%8,%9}, {%0,%1,%2,%3};\n"
        : "+f"(c[0]), "+f"(c[1]), "+f"(c[2]), "+f"(c[3])
        : "r"(a[0]), "r"(a[1]), "r"(a[2]), "r"(a[3]), "r"(b[0]), "r"(b[1]));
}

// pack two floats -> bf16x2 (lo = first k element)
__device__ __forceinline__ uint32_t packbf(float lo, float hi)
{
    uint32_t r;
    asm("cvt.rn.bf16x2.f32 %0, %1, %2;" : "=r"(r) : "f"(hi), "f"(lo));
    return r;
}

__device__ __forceinline__ float fex2(float x)
{
    float y;
    asm("ex2.approx.f32 %0, %1;" : "=f"(y) : "f"(x));
    return y;
}

constexpr int AST = 132;   // A/T smem stride (u32)
constexpr int BST = 20;    // B-chunk smem stride

// one 16-k-slab of mma: A-src (stride AST), B-chunk (stride BST)
// Warp tile = (MF*16) x 32 rows/cols.
template<int MF>
__device__ __forceinline__ void mma_slab(const uint32_t* S, const uint32_t* Bb,
                                         float acc[MF][4][4],
                                         int wm, int wn, int g, int tig, int kt)
{
#pragma unroll
    for (int k8s = 0; k8s < 2; ++k8s) {
        const int kk = kt * 16 + k8s * 8;
        uint32_t af[MF][4];
#pragma unroll
        for (int mf = 0; mf < MF; ++mf) {
            const uint32_t* pa = S + (wm * (16 * MF) + mf * 16 + g) * AST + kk + tig;
            af[mf][0] = pa[0];
            af[mf][1] = pa[8 * AST];
            af[mf][2] = pa[4];
            af[mf][3] = pa[8 * AST + 4];
        }
        uint32_t bf[4][2];
#pragma unroll
        for (int nf = 0; nf < 4; ++nf) {
            const uint32_t* pb = Bb + (wn * 32 + nf * 8 + g) * BST + k8s * 8 + tig;
            bf[nf][0] = pb[0];
            bf[nf][1] = pb[4];
        }
#pragma unroll
        for (int mf = 0; mf < MF; ++mf)
#pragma unroll
            for (int nf = 0; nf < 4; ++nf)
                mma_tf32(acc[mf][nf], af[mf], bf[nf]);
    }
}

// epilogue shared by gemm_ar / mlp_fused
template<int MF, bool RELU, bool RESID, bool STATS>
__device__ __forceinline__ void gemm_epilogue(
    float acc[MF][4][4], const float* bias, const float* resid,
    float* C, int ldc, int m0, int n0,
    int wm, int wn, int g, int tig, int tid,
    float* stats, float* sst /* 256-float smem scratch */)
{
    float cs[8], cq[8];
    if (STATS) {
#pragma unroll
        for (int j = 0; j < 8; ++j) { cs[j] = 0.f; cq[j] = 0.f; }
    }
#pragma unroll
    for (int mf = 0; mf < MF; ++mf) {
#pragma unroll
        for (int nf = 0; nf < 4; ++nf) {
            int row = m0 + wm * (16 * MF) + mf * 16 + g;
            int col = n0 + wn * 32 + nf * 8 + 2 * tig;
            float b0 = bias[col], b1 = bias[col + 1];
            float o00 = acc[mf][nf][0] + b0, o01 = acc[mf][nf][1] + b1;
            float o10 = acc[mf][nf][2] + b0, o11 = acc[mf][nf][3] + b1;
            if (RELU) {
                o00 = fmaxf(o00, 0.f); o01 = fmaxf(o01, 0.f);
                o10 = fmaxf(o10, 0.f); o11 = fmaxf(o11, 0.f);
            }
            if (RESID) {
                float2 r0 = *(const float2*)(resid + (size_t)row * ldc + col);
                float2 r1 = *(const float2*)(resid + (size_t)(row + 8) * ldc + col);
                o00 += r0.x; o01 += r0.y;
                o10 += r1.x; o11 += r1.y;
            }
            if (STATS) {
                cs[nf*2]   += o00 + o10;
                cs[nf*2+1] += o01 + o11;
                cq[nf*2]   += o00*o00 + o10*o10;
                cq[nf*2+1] += o01*o01 + o11*o11;
            }
            *(float2*)(C + (size_t)row * ldc + col)       = make_float2(o00, o01);
            *(float2*)(C + (size_t)(row + 8) * ldc + col) = make_float2(o10, o11);
        }
    }
    if (STATS) {
        __syncthreads();
        sst[tid] = 0.f;
        __syncthreads();
#pragma unroll
        for (int j = 0; j < 8; ++j) {
            int col = wn * 32 + (j >> 1) * 8 + 2 * tig + (j & 1);
            atomicAdd(&sst[col],       cs[j]);
            atomicAdd(&sst[128 + col], cq[j]);
        }
        __syncthreads();
        atomicAdd(&stats[tid], sst[tid]);
    }
}

// =====================================================================
// A-resident GEMM (K=128): C = A[128rows,128] @ B^T + bias (+resid)(+stats)
// Double-buffered B chunks: ONE sync per k-chunk. MF=4 (128-row tiles).
// =====================================================================
constexpr int GEMM_AR_SMEM = (128 * AST + 2 * 128 * BST) * 4;

template<bool RESID, bool STATS>
__global__ void __launch_bounds__(256, 2)
gemm_ar(const float* __restrict__ A,
        const float* __restrict__ B,
        const float* __restrict__ bias,
        const float* __restrict__ resid,
        float* __restrict__ C, int ldc,
        float* __restrict__ stats)
{
    extern __shared__ uint32_t sm[];
    uint32_t* Abuf = sm;               // [128][AST]
    uint32_t* Bb0  = sm + 128 * AST;   // stage 0
    uint32_t* Bb1  = Bb0 + 128 * BST;  // stage 1

    const int tid = threadIdx.x;
    const int lane = tid & 31, warp = tid >> 5;
    const int wm = warp >> 2, wn = warp & 3;
    const int g = lane >> 2, tig = lane & 3;
    const int m0 = blockIdx.x * 128;
    const int n0 = blockIdx.y * 128;
    const int i0 = tid, i1 = tid + 256;
    const float* Bp0 = B + (size_t)(n0 + (i0 >> 2)) * 128 + (i0 & 3) * 4;
    const float* Bp1 = B + (size_t)(n0 + (i1 >> 2)) * 128 + (i1 & 3) * 4;
    const int o0 = (i0 >> 2) * BST + (i0 & 3) * 4;   // ELEMENT offsets
    const int o1 = (i1 >> 2) * BST + (i1 & 3) * 4;

#pragma unroll
    for (int it = 0; it < 16; ++it) {
        int idx = tid + it * 256;
        int r = idx >> 5, c4 = (idx & 31) * 4;
        float4 v = *(const float4*)(A + (size_t)(m0 + r) * 128 + c4);
        uint32_t* d = Abuf + r * AST + c4;
        d[0] = to_tf32(v.x); d[1] = to_tf32(v.y);
        d[2] = to_tf32(v.z); d[3] = to_tf32(v.w);
    }

    float acc[4][4][4];
#pragma unroll
    for (int i = 0; i < 4; ++i)
#pragma unroll
        for (int j = 0; j < 4; ++j)
#pragma unroll
            for (int r = 0; r < 4; ++r) acc[i][j][r] = 0.f;

    // chunk 0 -> stage 0, prefetch chunk 1
    float4 pre0 = *(const float4*)(Bp0);
    float4 pre1 = *(const float4*)(Bp1);
    {
        uint32_t* d0 = Bb0 + o0;
        d0[0] = to_tf32(pre0.x); d0[1] = to_tf32(pre0.y);
        d0[2] = to_tf32(pre0.z); d0[3] = to_tf32(pre0.w);
        uint32_t* d1 = Bb0 + o1;
        d1[0] = to_tf32(pre1.x); d1[1] = to_tf32(pre1.y);
        d1[2] = to_tf32(pre1.z); d1[3] = to_tf32(pre1.w);
    }
    pre0 = *(const float4*)(Bp0 + 16);
    pre1 = *(const float4*)(Bp1 + 16);
    __syncthreads();

    for (int kt = 0; kt < 8; ++kt) {
        if (kt < 7) {
            uint32_t* stg = (kt & 1) ? Bb0 : Bb1;   // stage (kt+1)&1
            uint32_t* d0 = stg + o0;
            d0[0] = to_tf32(pre0.x); d0[1] = to_tf32(pre0.y);
            d0[2] = to_tf32(pre0.z); d0[3] = to_tf32(pre0.w);
            uint32_t* d1 = stg + o1;
            d1[0] = to_tf32(pre1.x); d1[1] = to_tf32(pre1.y);
            d1[2] = to_tf32(pre1.z); d1[3] = to_tf32(pre1.w);
            if (kt < 6) {
                pre0 = *(const float4*)(Bp0 + (kt + 2) * 16);
                pre1 = *(const float4*)(Bp1 + (kt + 2) * 16);
            }
        }
        mma_slab<4>(Abuf, (kt & 1) ? Bb1 : Bb0, acc, wm, wn, g, tig, kt);
        if (kt < 7) __syncthreads();
    }

    gemm_epilogue<4, false, RESID, STATS>(acc, bias, resid, C, ldc, m0, n0,
                                          wm, wn, g, tig, tid, stats, (float*)Bb0);
}

// =====================================================================
// Fused MLP: C = relu(A @ W1 + b1) @ W2 + b2 (+resid)(+stats)
// 64-row M-tiles (MF=2), occupancy 2, double-buffered B chunks.
// =====================================================================
constexpr int MROWS = 64;
constexpr int MLP_SMEM = (2 * MROWS * AST + 2 * 128 * BST) * 4;   // ~86KB

template<int NC, bool STATS>
__global__ void __launch_bounds__(256, 2)
mlp_fused(const float* __restrict__ A,
          const float* __restrict__ W1, const float* __restrict__ b1,
          const float* __restrict__ W2, const float* __restrict__ b2,
          const float* __restrict__ resid,
          float* __restrict__ C,
          float* __restrict__ stats)
{
    extern __shared__ uint32_t sm[];
    uint32_t* Abuf = sm;                     // [64][AST]
    uint32_t* Tbuf = sm + MROWS * AST;       // [64][AST]
    uint32_t* Bb0  = sm + 2 * MROWS * AST;   // stage 0
    uint32_t* Bb1  = Bb0 + 128 * BST;        // stage 1

    const int tid = threadIdx.x;
    const int lane = tid & 31, warp = tid >> 5;
    const int wm = warp >> 2, wn = warp & 3;
    const int g = lane >> 2, tig = lane & 3;
    const int m0 = blockIdx.x * MROWS;
    const int ldw1 = NC * 128;

    const int kk = tid >> 7;        // 0..1
    const int nn2 = tid & 127;      // n col
    const int ob = nn2 * BST + kk;  // ELEMENT store offset base

    // stage A strip: 64 rows x 128 cols = 2048 float4
#pragma unroll
    for (int it = 0; it < 8; ++it) {
        int idx = tid + it * 256;
        int r = idx >> 5, c4 = (idx & 31) * 4;
        float4 v = *(const float4*)(A + (size_t)(m0 + r) * 128 + c4);
        uint32_t* d = Abuf + r * AST + c4;
        d[0] = to_tf32(v.x); d[1] = to_tf32(v.y);
        d[2] = to_tf32(v.z); d[3] = to_tf32(v.w);
    }

    float co[2][4][4];
#pragma unroll
    for (int i = 0; i < 2; ++i)
#pragma unroll
        for (int j = 0; j < 4; ++j)
#pragma unroll
            for (int r = 0; r < 4; ++r) co[i][j][r] = 0.f;

#pragma unroll
    for (int nc = 0; nc < NC; ++nc) {
        // ============ phase 1: c1 = A @ W1[:, nc*128..] ============
        float c1[2][4][4];
#pragma unroll
        for (int i = 0; i < 2; ++i)
#pragma unroll
            for (int j = 0; j < 4; ++j)
#pragma unroll
                for (int r = 0; r < 4; ++r) c1[i][j][r] = 0.f;

        const float* Wp = W1 + nc * 128 + nn2;
        float pre[8];
#pragma unroll
        for (int j = 0; j < 8; ++j)
            pre[j] = Wp[(size_t)(j * 2 + kk) * ldw1];
        if (nc) __syncthreads();  // protect Bb0 from previous phase-2 kt=6 reads
#pragma unroll
        for (int j = 0; j < 8; ++j)
            Bb0[ob + j * 2] = to_tf32(pre[j]);
#pragma unroll
        for (int j = 0; j < 8; ++j)
            pre[j] = Wp[(size_t)(16 + j * 2 + kk) * ldw1];
        __syncthreads();

        for (int kt = 0; kt < 8; ++kt) {
            if (kt < 7) {
                uint32_t* stg = (kt & 1) ? Bb0 : Bb1;
#pragma unroll
                for (int j = 0; j < 8; ++j)
                    stg[ob + j * 2] = to_tf32(pre[j]);
                if (kt < 6) {
#pragma unroll
                    for (int j = 0; j < 8; ++j)
                        pre[j] = Wp[(size_t)((kt + 2) * 16 + j * 2 + kk) * ldw1];
                }
            }
            mma_slab<2>(Abuf, (kt & 1) ? Bb1 : Bb0, c1, wm, wn, g, tig, kt);
            if (kt < 7) __syncthreads();
        }

        // write hidden tile: relu(c1 + b1chunk) -> Tbuf (tf32)
#pragma unroll
        for (int mf = 0; mf < 2; ++mf) {
#pragma unroll
            for (int nf = 0; nf < 4; ++nf) {
                int row = wm * 32 + mf * 16 + g;
                int col = wn * 32 + nf * 8 + 2 * tig;
                float bb0 = b1[nc * 128 + col], bb1 = b1[nc * 128 + col + 1];
                Tbuf[row * AST + col]           = to_tf32(fmaxf(c1[mf][nf][0] + bb0, 0.f));
                Tbuf[row * AST + col + 1]       = to_tf32(fmaxf(c1[mf][nf][1] + bb1, 0.f));
                Tbuf[(row + 8) * AST + col]     = to_tf32(fmaxf(c1[mf][nf][2] + bb0, 0.f));
                Tbuf[(row + 8) * AST + col + 1] = to_tf32(fmaxf(c1[mf][nf][3] + bb1, 0.f));
            }
        }

        // ============ phase 2: co += T @ W2[nc*128.., :] ============
        const float* W2p = W2 + (size_t)nc * 128 * 128 + nn2;
#pragma unroll
        for (int j = 0; j < 8; ++j)
            pre[j] = W2p[(size_t)(j * 2 + kk) * 128];
        __syncthreads();  // all warps past phase-1 kt=6 mma (Bb0 free)
#pragma unroll
        for (int j = 0; j < 8; ++j)
            Bb0[ob + j * 2] = to_tf32(pre[j]);
#pragma unroll
        for (int j = 0; j < 8; ++j)
            pre[j] = W2p[(size_t)(16 + j * 2 + kk) * 128];
        __syncthreads();  // Tbuf writes visible + Bb1 free (phase-1 kt=7 done)

        for (int kt = 0; kt < 8; ++kt) {
            if (kt < 7) {
                uint32_t* stg = (kt & 1) ? Bb0 : Bb1;
#pragma unroll
                for (int j = 0; j < 8; ++j)
                    stg[ob + j * 2] = to_tf32(pre[j]);
                if (kt < 6) {
#pragma unroll
                    for (int j = 0; j < 8; ++j)
                        pre[j] = W2p[(size_t)((kt + 2) * 16 + j * 2 + kk) * 128];
                }
            }
            mma_slab<2>(Tbuf, (kt & 1) ? Bb1 : Bb0, co, wm, wn, g, tig, kt);
            if (kt < 7) __syncthreads();
        }
    }

    gemm_epilogue<2, false, true, STATS>(co, b2, resid, C, 128, m0, 0,
                                         wm, wn, g, tig, tid, stats, (float*)Bb0);
}

// =====================================================================
// Flash-style BF16 attention v4: exp2-domain scores, occupancy 3.
// =====================================================================
constexpr int KP_ST = 12;
constexpr int VP_ST = 24;
constexpr int ATTN_SMEM = (512 * KP_ST + 256 * VP_ST) * 4;   // 48KB

__global__ void __launch_bounds__(256, 3)
attn_mma(const float* __restrict__ qkv, float* __restrict__ ao)
{
    extern __shared__ uint32_t sm[];
    uint32_t* Ksp = sm;                   // [512 kv][12]  bf16x2 pairs along d
    uint32_t* Vsp = sm + 512 * KP_ST;     // [256 kvpair][24] bf16x2 pairs along kv

    const int tid  = threadIdx.x;
    const int lane = tid & 31;
    const int warp = tid >> 5;
    const int g    = lane >> 2;
    const int tig  = lane & 3;
    const int b    = blockIdx.x;
    const int gi = b >> 4, h = (b >> 1) & 7, half = b & 1;
    const float* base = qkv + (size_t)gi * SEQ * 384;
    const int m0 = half * 256 + warp * 32;
    const float QSC = 0.25f * 1.44269504f;   // 1/sqrt(dh) * log2(e)

    for (int idx = tid; idx < 2048; idx += 256) {
        int r = idx >> 2, c4 = (idx & 3) * 4;
        float4 kv = *(const float4*)(base + (size_t)r * 384 + 128 + h * 16 + c4);
        Ksp[r * KP_ST + (c4 >> 1)]     = packbf(kv.x, kv.y);
        Ksp[r * KP_ST + (c4 >> 1) + 1] = packbf(kv.z, kv.w);
        if (idx < 1024) {
            int pr = r, dg = c4;
            float4 v0 = *(const float4*)(base + (size_t)(2 * pr)     * 384 + 256 + h * 16 + dg);
            float4 v1 = *(const float4*)(base + (size_t)(2 * pr + 1) * 384 + 256 + h * 16 + dg);
            uint32_t* vd = Vsp + pr * VP_ST + dg;
            vd[0] = packbf(v0.x, v1.x);
            vd[1] = packbf(v0.y, v1.y);
            vd[2] = packbf(v0.z, v1.z);
            vd[3] = packbf(v0.w, v1.w);
        }
    }

    uint32_t qa[2][4];
#pragma unroll
    for (int mt = 0; mt < 2; ++mt) {
        const float* qp = base + (size_t)(m0 + mt * 16 + g) * 384 + h * 16;
        float2 a0 = *(const float2*)(qp + 2 * tig);
        float2 a1 = *(const float2*)(qp + 8 * 384 + 2 * tig);
        float2 a2 = *(const float2*)(qp + 2 * tig + 8);
        float2 a3 = *(const float2*)(qp + 8 * 384 + 2 * tig + 8);
        qa[mt][0] = packbf(a0.x * QSC, a0.y * QSC);
        qa[mt][1] = packbf(a1.x * QSC, a1.y * QSC);
        qa[mt][2] = packbf(a2.x * QSC, a2.y * QSC);
        qa[mt][3] = packbf(a3.x * QSC, a3.y * QSC);
    }
    __syncthreads();

    float o[2][2][4];
    float lrow[2][2];
#pragma unroll
    for (int mt = 0; mt < 2; ++mt) {
        lrow[mt][0] = 0.f; lrow[mt][1] = 0.f;
#pragma unroll
        for (int nt = 0; nt < 2; ++nt)
#pragma unroll
            for (int r = 0; r < 4; ++r) o[mt][nt][r] = 0.f;
    }

    for (int j = 0; j < 16; ++j) {
        const int n0 = j * 32;
        uint32_t ps[2][2][4];

#pragma unroll
        for (int nt = 0; nt < 4; ++nt) {
            uint32_t bk[2];
            {
                const uint32_t* kp = Ksp + (n0 + nt * 8 + g) * KP_ST + tig;
                bk[0] = kp[0];
                bk[1] = kp[4];
            }
#pragma unroll
            for (int mt = 0; mt < 2; ++mt) {
                float c[4] = {0.f, 0.f, 0.f, 0.f};
                mma_bf16(c, qa[mt], bk);
                float p0 = fex2(c[0]);
                float p1 = fex2(c[1]);
                float p2 = fex2(c[2]);
                float p3 = fex2(c[3]);
                lrow[mt][0] += p0 + p1;
                lrow[mt][1] += p2 + p3;
                ps[mt][nt >> 1][(nt & 1) * 2 + 0] = packbf(p0, p1);
                ps[mt][nt >> 1][(nt & 1) * 2 + 1] = packbf(p2, p3);
            }
        }

#pragma unroll
        for (int c = 0; c < 2; ++c) {
            const int prb = (n0 >> 1) + c * 8;
#pragma unroll
            for (int nt = 0; nt < 2; ++nt) {
                uint32_t bv[2];
                const uint32_t* vp = Vsp + (prb + tig) * VP_ST + nt * 8 + g;
                bv[0] = vp[0];
                bv[1] = vp[4 * VP_ST];
#pragma unroll
                for (int mt = 0; mt < 2; ++mt)
                    mma_bf16(o[mt][nt], ps[mt][c], bv);
            }
        }
    }

#pragma unroll
    for (int mt = 0; mt < 2; ++mt) {
        float l0 = lrow[mt][0], l1 = lrow[mt][1];
        l0 += __shfl_xor_sync(0xffffffffu, l0, 1);
        l0 += __shfl_xor_sync(0xffffffffu, l0, 2);
        l1 += __shfl_xor_sync(0xffffffffu, l1, 1);
        l1 += __shfl_xor_sync(0xffffffffu, l1, 2);
        float i0 = 1.f / l0, i1 = 1.f / l1;
        int grow = gi * SEQ + m0 + mt * 16 + g;
#pragma unroll
        for (int nt = 0; nt < 2; ++nt) {
            int col = h * 16 + nt * 8 + 2 * tig;
            *(float2*)(ao + (size_t)grow * DD + col) =
                make_float2(o[mt][nt][0] * i0, o[mt][nt][1] * i0);
            *(float2*)(ao + (size_t)(grow + 8) * DD + col) =
                make_float2(o[mt][nt][2] * i1, o[mt][nt][3] * i1);
        }
    }
}

// =====================================================================
// BatchNorm applies
// =====================================================================
__device__ __forceinline__ void bn_coef(const float* stats, const float* gamma,
                                        const float* beta, int col,
                                        float& sc, float& sh)
{
    float mean = stats[col] * (1.f / (float)NN);
    float var  = stats[128 + col] * (1.f / (float)NN) - mean * mean;
    sc = gamma[col] * rsqrtf(var + 1e-5f);
    sh = beta[col] - mean * sc;
}

__global__ void __launch_bounds__(256)
bn_apply_one(const float* __restrict__ X, const float* __restrict__ stats,
             const float* __restrict__ gamma, const float* __restrict__ beta,
             float* __restrict__ out)
{
    int col = threadIdx.x & 127;
    int half = threadIdx.x >> 7;
    float sc, sh;
    bn_coef(stats, gamma, beta, col, sc, sh);
    int row0 = blockIdx.x * 128 + half * 64;
    size_t off = (size_t)row0 * DD + col;
#pragma unroll 4
    for (int r = 0; r < 64; ++r)
        out[off + r * DD] = X[off + r * DD] * sc + sh;
}

__global__ void __launch_bounds__(256)
bn_apply_dual(const float* __restrict__ ha, const float* __restrict__ statsA,
              const float* __restrict__ ga, const float* __restrict__ ba,
              const float* __restrict__ hl, const float* __restrict__ statsL,
              const float* __restrict__ gl, const float* __restrict__ bl,
              float* __restrict__ out)
{
    int col = threadIdx.x & 127;
    int half = threadIdx.x >> 7;
    float scA, shA, scL, shL;
    bn_coef(statsA, ga, ba, col, scA, shA);
    bn_coef(statsL, gl, bl, col, scL, shL);
    int row0 = blockIdx.x * 128 + half * 64;
    size_t off = (size_t)row0 * DD + col;
#pragma unroll 4
    for (int r = 0; r < 64; ++r)
        out[off + r * DD] = ha[off + r * DD] * scA + shA
                          + hl[off + r * DD] * scL + shL;
}

// =====================================================================
// Host launcher — two-stream fork/join captured as a branching graph.
// =====================================================================
extern "C" void kernel_launch(void* const* d_in, const int* in_sizes, int n_in,
                              void* d_out, int out_size)
{
    const float* x          = (const float*)d_in[0];
    const int*   edge_index = (const int*)  d_in[1];
    const float* edge_attr  = (const float*)d_in[2];
    const float* gin_w1     = (const float*)d_in[3];
    const float* gin_b1     = (const float*)d_in[4];
    const float* gin_w2     = (const float*)d_in[5];
    const float* gin_b2     = (const float*)d_in[6];
    const float* bn1l_g     = (const float*)d_in[7];
    const float* bn1l_b     = (const float*)d_in[8];
    const float* in_proj_w  = (const float*)d_in[9];
    const float* in_proj_b  = (const float*)d_in[10];
    const float* out_proj_w = (const float*)d_in[11];
    const float* out_proj_b = (const float*)d_in[12];
    const float* bn1a_g     = (const float*)d_in[13];
    const float* bn1a_b     = (const float*)d_in[14];
    const float* ff_w1      = (const float*)d_in[15];
    const float* ff_b1      = (const float*)d_in[16];
    const float* ff_w2      = (const float*)d_in[17];
    const float* ff_b2      = (const float*)d_in[18];
    const float* bn2_g      = (const float*)d_in[19];
    const float* bn2_b      = (const float*)d_in[20];
    float* out = (float*)d_out;

    // One-time resources (created outside capture on the correctness call).
    static cudaStream_t sB = nullptr;
    static cudaEvent_t evFork = nullptr, evJoin = nullptr;
    if (sB == nullptr) {
        cudaStreamCreateWithFlags(&sB, cudaStreamNonBlocking);
        cudaEventCreateWithFlags(&evFork, cudaEventDisableTiming);
        cudaEventCreateWithFlags(&evJoin, cudaEventDisableTiming);
        cudaFuncSetAttribute(attn_mma, cudaFuncAttributeMaxDynamicSharedMemorySize, ATTN_SMEM);
        cudaFuncSetAttribute(gemm_ar<false, false>, cudaFuncAttributeMaxDynamicSharedMemorySize, GEMM_AR_SMEM);
        cudaFuncSetAttribute(gemm_ar<true,  true >, cudaFuncAttributeMaxDynamicSharedMemorySize, GEMM_AR_SMEM);
        cudaFuncSetAttribute(mlp_fused<1, true>, cudaFuncAttributeMaxDynamicSharedMemorySize, MLP_SMEM);
        cudaFuncSetAttribute(mlp_fused<2, true>, cudaFuncAttributeMaxDynamicSharedMemorySize, MLP_SMEM);
    }

    float *z, *hl, *qkvb, *ao, *ha, *h, *h2, *stats;
    int *deg, *off, *pos, *eid;
    cudaGetSymbolAddress((void**)&z,    g_z);
    cudaGetSymbolAddress((void**)&hl,   g_hl);
    cudaGetSymbolAddress((void**)&qkvb, g_qkv);
    cudaGetSymbolAddress((void**)&ao,   g_ao);
    cudaGetSymbolAddress((void**)&ha,   g_ha);
    cudaGetSymbolAddress((void**)&h,    g_h);
    cudaGetSymbolAddress((void**)&h2,   g_h2);
    cudaGetSymbolAddress((void**)&stats, g_stats);
    cudaGetSymbolAddress((void**)&deg,  g_deg);
    cudaGetSymbolAddress((void**)&off,  g_off);
    cudaGetSymbolAddress((void**)&pos,  g_pos);
    cudaGetSymbolAddress((void**)&eid,  g_eid);

    const int* src = edge_index;
    const int* dst = edge_index + EE;
    const dim3 blk(256);
    const int GB = NN / 128;     // 128-row tiles (gemm_ar)
    const int GB64 = NN / 64;    // 64-row tiles (mlp_fused)

    float* stats_hl = stats;
    float* stats_ha = stats + 256;
    float* stats_h2 = stats + 512;

    // ---- common prologue on null stream ----
    zero_misc<<<64, blk>>>(deg, stats);                                            // 0

    // ---- fork: stream B = attention branch ----
    cudaEventRecord(evFork, 0);
    cudaStreamWaitEvent(sB, evFork, 0);

    gemm_ar<false, false><<<dim3(GB, 3), blk, GEMM_AR_SMEM, sB>>>(
        x, in_proj_w, in_proj_b, nullptr, qkvb, 384, nullptr);                     // 1 (B)
    count_kernel<<<EE / 256, blk>>>(dst, deg);                                     // 2 (A)
    attn_mma<<<NGR * NH * 2, blk, ATTN_SMEM, sB>>>(qkvb, ao);                      // 3 (B) <- profiled
    scan_kernel<<<1, 1024>>>(deg, off, pos);                                       // 4 (A)
    scatter_kernel<<<EE / 256, blk>>>(dst, pos, eid);                              // 5 (A)
    gemm_ar<true, true><<<dim3(GB, 1), blk, GEMM_AR_SMEM, sB>>>(
        ao, out_proj_w, out_proj_b, x, ha, 128, stats_ha);                         // 6 (B)
    aggr_kernel<<<NN / 8, blk>>>(x, src, edge_attr, off, eid, z);                  // 7 (A)
    mlp_fused<1, true><<<GB64, blk, MLP_SMEM>>>(z, gin_w1, gin_b1, gin_w2, gin_b2,
                                                x, hl, stats_hl);                  // 8 (A)

    // ---- join ----
    cudaEventRecord(evJoin, sB);
    cudaStreamWaitEvent(0, evJoin, 0);

    bn_apply_dual<<<128, blk>>>(ha, stats_ha, bn1a_g, bn1a_b,
                                hl, stats_hl, bn1l_g, bn1l_b, h);                  // 9
    mlp_fused<2, true><<<GB64, blk, MLP_SMEM>>>(h, ff_w1, ff_b1, ff_w2, ff_b2,
                                                h, h2, stats_h2);                  // 10
    bn_apply_one<<<128, blk>>>(h2, stats_h2, bn2_g, bn2_b, out);                   // 11
}

// round 13
// speedup vs baseline: 1.0775x; 1.0775x over previous
#include <cuda_runtime.h>
#include <cuda_bf16.h>
#include <math.h>
#include <stdint.h>

// Problem constants
constexpr int NN  = 16384;   // nodes
constexpr int DD  = 128;     // dim
constexpr int EE  = 262144;  // edges
constexpr int SEQ = 512;     // nodes per graph
constexpr int NGR = 32;      // graphs
constexpr int NH  = 8;       // heads (dh = 16)

// ---------------- scratch ----------------
__device__ float g_z   [NN * DD];
__device__ float g_hl  [NN * DD];
__device__ float g_qkv [NN * 3 * DD];
__device__ float g_ao  [NN * DD];
__device__ float g_ha  [NN * DD];
__device__ float g_h   [NN * DD];
__device__ float g_h2  [NN * DD];
__device__ float g_stats[768];
__device__ int   g_deg [NN];
__device__ int   g_off [NN + 1];
__device__ int   g_pos [NN];
__device__ int   g_eid [EE];

// =====================================================================
__global__ void zero_misc(int* deg, float* stats)
{
    int i = blockIdx.x * 256 + threadIdx.x;
    deg[i] = 0;
    if (i < 768) stats[i] = 0.f;
}

// =====================================================================
// CSR build by dst:  count -> scan -> scatter
// =====================================================================
__global__ void count_kernel(const int* __restrict__ dst, int* __restrict__ deg)
{
    int e = blockIdx.x * 256 + threadIdx.x;
    atomicAdd(&deg[dst[e]], 1);
}

__global__ void __launch_bounds__(1024)
scan_kernel(const int* __restrict__ deg, int* __restrict__ off, int* __restrict__ pos)
{
    __shared__ int buf[2][1024];
    int t = threadIdx.x;
    int base = t * 16;
    int loc[16];
    int sum = 0;
#pragma unroll
    for (int i = 0; i < 16; ++i) { loc[i] = sum; sum += deg[base + i]; }
    buf[0][t] = sum;
    __syncthreads();
    int sel = 0;
    for (int d = 1; d < 1024; d <<= 1) {
        int v = buf[sel][t] + (t >= d ? buf[sel][t - d] : 0);
        buf[sel ^ 1][t] = v;
        sel ^= 1;
        __syncthreads();
    }
    int excl = buf[sel][t] - sum;
#pragma unroll
    for (int i = 0; i < 16; ++i) {
        int o = excl + loc[i];
        off[base + i] = o;
        pos[base + i] = o;
    }
    if (t == 1023) off[NN] = excl + sum;
}

__global__ void scatter_kernel(const int* __restrict__ dst, int* __restrict__ pos,
                               int* __restrict__ eid)
{
    int e = blockIdx.x * 256 + threadIdx.x;
    int p = atomicAdd(&pos[dst[e]], 1);
    eid[p] = e;
}

// =====================================================================
// Gather aggregation: z = x + sum_{e -> node} relu(x[src[e]] + ea[e])
// =====================================================================
__global__ void __launch_bounds__(256)
aggr_kernel(const float* __restrict__ x, const int* __restrict__ src,
            const float* __restrict__ ea, const int* __restrict__ off,
            const int* __restrict__ eid, float* __restrict__ z)
{
    int node = blockIdx.x * 8 + (threadIdx.x >> 5);
    int lane = threadIdx.x & 31;
    int beg = off[node], end = off[node + 1];
    const float4* x4  = (const float4*)x;
    const float4* ea4 = (const float4*)ea;
    float4 acc = make_float4(0.f, 0.f, 0.f, 0.f);
#pragma unroll 2
    for (int i = beg; i < end; ++i) {
        int e = __ldg(eid + i);
        int s = __ldg(src + e);
        float4 a = x4[(size_t)s * 32 + lane];
        float4 b = ea4[(size_t)e * 32 + lane];
        acc.x += fmaxf(a.x + b.x, 0.f);
        acc.y += fmaxf(a.y + b.y, 0.f);
        acc.z += fmaxf(a.z + b.z, 0.f);
        acc.w += fmaxf(a.w + b.w, 0.f);
    }
    float4 xv = x4[(size_t)node * 32 + lane];
    ((float4*)z)[(size_t)node * 32 + lane] =
        make_float4(xv.x + acc.x, xv.y + acc.y, xv.z + acc.z, xv.w + acc.w);
}

// =====================================================================
// mma helpers
// =====================================================================
__device__ __forceinline__ uint32_t to_tf32(float f)
{
    uint32_t u;
    asm("cvt.rna.tf32.f32 %0, %1;" : "=r"(u) : "f"(f));
    return u;
}

__device__ __forceinline__ void mma_tf32(float c[4], const uint32_t a[4], const uint32_t b[2])
{
    asm volatile(
        "mma.sync.aligned.m16n8k8.row.col.f32.tf32.tf32.f32 "
        "{%0,%1,%2,%3}, {%4,%5,%6,%7}, {%8,%9}, {%0,%1,%2,%3};\n"
        : "+f"(c[0]), "+f"(c[1]), "+f"(c[2]), "+f"(c[3])
        : "r"(a[0]), "r"(a[1]), "r"(a[2]), "r"(a[3]), "r"(b[0]), "r"(b[1]));
}

__device__ __forceinline__ void mma_bf16(float c[4], const uint32_t a[4], const uint32_t b[2])
{
    asm volatile(
        "mma.sync.aligned.m16n8k16.row.col.f32.bf16.bf16.f32 "
        "{%0,%1,%2,%3}, {%4,%5,%6,%7}, {%8,%9}, {%0,%1,%2,%3};\n"
        : "+f"(c[0]), "+f"(c[1]), "+f"(c[2]), "+f"(c[3])
        : "r"(a[0]), "r"(a[1]), "r"(a[2]), "r"(a[3]), "r"(b[0]), "r"(b[1]));
}

__device__ __forceinline__ uint32_t packbf(float lo, float hi)
{
    uint32_t r;
    asm("cvt.rn.bf16x2.f32 %0, %1, %2;" : "=r"(r) : "f"(hi), "f"(lo));
    return r;
}

__device__ __forceinline__ float fex2(float x)
{
    float y;
    asm("ex2.approx.f32 %0, %1;" : "=f"(y) : "f"(x));
    return y;
}

constexpr int AST  = 132;   // A/T smem stride (u32)
constexpr int BST  = 20;    // [n][k] B-chunk stride (gemm_ar)
constexpr int BSTK = 132;   // [k][n] B-chunk stride (mlp_fused)

// one 16-k-slab: A-src (stride AST), B-chunk [n][k] (stride BST)
__device__ __forceinline__ void mma_slab16(const uint32_t* S, const uint32_t* Bb,
                                           float acc[4][4][4],
                                           int wm, int wn, int g, int tig, int kt)
{
#pragma unroll
    for (int k8s = 0; k8s < 2; ++k8s) {
        const int kk = kt * 16 + k8s * 8;
        uint32_t af[4][4];
#pragma unroll
        for (int mf = 0; mf < 4; ++mf) {
            const uint32_t* pa = S + (wm * 64 + mf * 16 + g) * AST + kk + tig;
            af[mf][0] = pa[0];
            af[mf][1] = pa[8 * AST];
            af[mf][2] = pa[4];
            af[mf][3] = pa[8 * AST + 4];
        }
        uint32_t bf[4][2];
#pragma unroll
        for (int nf = 0; nf < 4; ++nf) {
            const uint32_t* pb = Bb + (wn * 32 + nf * 8 + g) * BST + k8s * 8 + tig;
            bf[nf][0] = pb[0];
            bf[nf][1] = pb[4];
        }
#pragma unroll
        for (int mf = 0; mf < 4; ++mf)
#pragma unroll
            for (int nf = 0; nf < 4; ++nf)
                mma_tf32(acc[mf][nf], af[mf], bf[nf]);
    }
}

// one 16-k-slab: A-src (stride AST), B-chunk [k][n] (stride BSTK; 16 rows)
__device__ __forceinline__ void mma_slab16_kn(const uint32_t* S, const uint32_t* Bkn,
                                              float acc[4][4][4],
                                              int wm, int wn, int g, int tig, int kt)
{
#pragma unroll
    for (int k8s = 0; k8s < 2; ++k8s) {
        const int kk = kt * 16 + k8s * 8;
        uint32_t af[4][4];
#pragma unroll
        for (int mf = 0; mf < 4; ++mf) {
            const uint32_t* pa = S + (wm * 64 + mf * 16 + g) * AST + kk + tig;
            af[mf][0] = pa[0];
            af[mf][1] = pa[8 * AST];
            af[mf][2] = pa[4];
            af[mf][3] = pa[8 * AST + 4];
        }
        uint32_t bf[4][2];
        const uint32_t* pb0 = Bkn + (k8s * 8 + tig) * BSTK;
        const uint32_t* pb1 = pb0 + 4 * BSTK;
#pragma unroll
        for (int nf = 0; nf < 4; ++nf) {
            int n = wn * 32 + nf * 8 + g;
            bf[nf][0] = pb0[n];
            bf[nf][1] = pb1[n];
        }
#pragma unroll
        for (int mf = 0; mf < 4; ++mf)
#pragma unroll
            for (int nf = 0; nf < 4; ++nf)
                mma_tf32(acc[mf][nf], af[mf], bf[nf]);
    }
}

// epilogue shared by gemm_ar / mlp_fused (MF=4)
template<bool RELU, bool RESID, bool STATS>
__device__ __forceinline__ void gemm_epilogue(
    float acc[4][4][4], const float* bias, const float* resid,
    float* C, int ldc, int m0, int n0,
    int wm, int wn, int g, int tig, int tid,
    float* stats, float* sst)
{
    float cs[8], cq[8];
    if (STATS) {
#pragma unroll
        for (int j = 0; j < 8; ++j) { cs[j] = 0.f; cq[j] = 0.f; }
    }
#pragma unroll
    for (int mf = 0; mf < 4; ++mf) {
#pragma unroll
        for (int nf = 0; nf < 4; ++nf) {
            int row = m0 + wm * 64 + mf * 16 + g;
            int col = n0 + wn * 32 + nf * 8 + 2 * tig;
            float b0 = bias[col], b1 = bias[col + 1];
            float o00 = acc[mf][nf][0] + b0, o01 = acc[mf][nf][1] + b1;
            float o10 = acc[mf][nf][2] + b0, o11 = acc[mf][nf][3] + b1;
            if (RELU) {
                o00 = fmaxf(o00, 0.f); o01 = fmaxf(o01, 0.f);
                o10 = fmaxf(o10, 0.f); o11 = fmaxf(o11, 0.f);
            }
            if (RESID) {
                float2 r0 = *(const float2*)(resid + (size_t)row * ldc + col);
                float2 r1 = *(const float2*)(resid + (size_t)(row + 8) * ldc + col);
                o00 += r0.x; o01 += r0.y;
                o10 += r1.x; o11 += r1.y;
            }
            if (STATS) {
                cs[nf*2]   += o00 + o10;
                cs[nf*2+1] += o01 + o11;
                cq[nf*2]   += o00*o00 + o10*o10;
                cq[nf*2+1] += o01*o01 + o11*o11;
            }
            *(float2*)(C + (size_t)row * ldc + col)       = make_float2(o00, o01);
            *(float2*)(C + (size_t)(row + 8) * ldc + col) = make_float2(o10, o11);
        }
    }
    if (STATS) {
        __syncthreads();
        sst[tid] = 0.f;
        __syncthreads();
#pragma unroll
        for (int j = 0; j < 8; ++j) {
            int col = wn * 32 + (j >> 1) * 8 + 2 * tig + (j & 1);
            atomicAdd(&sst[col],       cs[j]);
            atomicAdd(&sst[128 + col], cq[j]);
        }
        __syncthreads();
        atomicAdd(&stats[tid], sst[tid]);
    }
}

// =====================================================================
// A-resident GEMM (K=128): C = A[128rows,128] @ B^T + bias (+resid)(+stats)
// Double-buffered B chunks, one sync per k-chunk. (unchanged from R11)
// =====================================================================
constexpr int GEMM_AR_SMEM = (128 * AST + 2 * 128 * BST) * 4;

template<bool RESID, bool STATS>
__global__ void __launch_bounds__(256, 2)
gemm_ar(const float* __restrict__ A,
        const float* __restrict__ B,
        const float* __restrict__ bias,
        const float* __restrict__ resid,
        float* __restrict__ C, int ldc,
        float* __restrict__ stats)
{
    extern __shared__ uint32_t sm[];
    uint32_t* Abuf = sm;
    uint32_t* Bb0  = sm + 128 * AST;
    uint32_t* Bb1  = Bb0 + 128 * BST;

    const int tid = threadIdx.x;
    const int lane = tid & 31, warp = tid >> 5;
    const int wm = warp >> 2, wn = warp & 3;
    const int g = lane >> 2, tig = lane & 3;
    const int m0 = blockIdx.x * 128;
    const int n0 = blockIdx.y * 128;
    const int i0 = tid, i1 = tid + 256;
    const float* Bp0 = B + (size_t)(n0 + (i0 >> 2)) * 128 + (i0 & 3) * 4;
    const float* Bp1 = B + (size_t)(n0 + (i1 >> 2)) * 128 + (i1 & 3) * 4;
    const int o0 = (i0 >> 2) * BST + (i0 & 3) * 4;
    const int o1 = (i1 >> 2) * BST + (i1 & 3) * 4;

#pragma unroll
    for (int it = 0; it < 16; ++it) {
        int idx = tid + it * 256;
        int r = idx >> 5, c4 = (idx & 31) * 4;
        float4 v = *(const float4*)(A + (size_t)(m0 + r) * 128 + c4);
        uint32_t* d = Abuf + r * AST + c4;
        d[0] = to_tf32(v.x); d[1] = to_tf32(v.y);
        d[2] = to_tf32(v.z); d[3] = to_tf32(v.w);
    }

    float acc[4][4][4];
#pragma unroll
    for (int i = 0; i < 4; ++i)
#pragma unroll
        for (int j = 0; j < 4; ++j)
#pragma unroll
            for (int r = 0; r < 4; ++r) acc[i][j][r] = 0.f;

    float4 pre0 = *(const float4*)(Bp0);
    float4 pre1 = *(const float4*)(Bp1);
    {
        uint32_t* d0 = Bb0 + o0;
        d0[0] = to_tf32(pre0.x); d0[1] = to_tf32(pre0.y);
        d0[2] = to_tf32(pre0.z); d0[3] = to_tf32(pre0.w);
        uint32_t* d1 = Bb0 + o1;
        d1[0] = to_tf32(pre1.x); d1[1] = to_tf32(pre1.y);
        d1[2] = to_tf32(pre1.z); d1[3] = to_tf32(pre1.w);
    }
    pre0 = *(const float4*)(Bp0 + 16);
    pre1 = *(const float4*)(Bp1 + 16);
    __syncthreads();

    for (int kt = 0; kt < 8; ++kt) {
        if (kt < 7) {
            uint32_t* stg = (kt & 1) ? Bb0 : Bb1;
            uint32_t* d0 = stg + o0;
            d0[0] = to_tf32(pre0.x); d0[1] = to_tf32(pre0.y);
            d0[2] = to_tf32(pre0.z); d0[3] = to_tf32(pre0.w);
            uint32_t* d1 = stg + o1;
            d1[0] = to_tf32(pre1.x); d1[1] = to_tf32(pre1.y);
            d1[2] = to_tf32(pre1.z); d1[3] = to_tf32(pre1.w);
            if (kt < 6) {
                pre0 = *(const float4*)(Bp0 + (kt + 2) * 16);
                pre1 = *(const float4*)(Bp1 + (kt + 2) * 16);
            }
        }
        mma_slab16(Abuf, (kt & 1) ? Bb1 : Bb0, acc, wm, wn, g, tig, kt);
        if (kt < 7) __syncthreads();
    }

    gemm_epilogue<false, RESID, STATS>(acc, bias, resid, C, ldc, m0, n0,
                                       wm, wn, g, tig, tid, stats, (float*)Bb0);
}

// =====================================================================
// Fused MLP: C = relu(A @ W1 + b1) @ W2 + b2 (+resid)(+stats)
// MF=4, 128-row tiles, occ 1. Weight chunks staged [k][n] with COALESCED
// float4 row loads (warp = one 512B row). Double-buffered, 1 sync/chunk.
// =====================================================================
constexpr int MLP_SMEM = (2 * 128 * AST + 2 * 16 * BSTK) * 4;   // ~152KB

template<int NC, bool STATS>
__global__ void __launch_bounds__(256, 1)
mlp_fused(const float* __restrict__ A,
          const float* __restrict__ W1, const float* __restrict__ b1,
          const float* __restrict__ W2, const float* __restrict__ b2,
          const float* __restrict__ resid,
          float* __restrict__ C,
          float* __restrict__ stats)
{
    extern __shared__ uint32_t sm[];
    uint32_t* Abuf = sm;                   // [128][AST]
    uint32_t* Tbuf = sm + 128 * AST;       // [128][AST]
    uint32_t* Bb0  = sm + 2 * 128 * AST;   // [16][BSTK] stage 0
    uint32_t* Bb1  = Bb0 + 16 * BSTK;      // [16][BSTK] stage 1

    const int tid = threadIdx.x;
    const int lane = tid & 31, warp = tid >> 5;
    const int wm = warp >> 2, wn = warp & 3;
    const int g = lane >> 2, tig = lane & 3;
    const int m0 = blockIdx.x * 128;
    const int ldw1 = NC * 128;

    // staging geometry: idx 0..511 float4s; row k = idx>>5 (0..15), col4 = idx&31
    const int i0 = tid, i1 = tid + 256;
    const int k0 = i0 >> 5, c40 = (i0 & 31) * 4;
    const int k1 = i1 >> 5, c41 = (i1 & 31) * 4;
    const int o0 = k0 * BSTK + c40;
    const int o1 = k1 * BSTK + c41;

#pragma unroll
    for (int it = 0; it < 16; ++it) {
        int idx = tid + it * 256;
        int r = idx >> 5, c4 = (idx & 31) * 4;
        float4 v = *(const float4*)(A + (size_t)(m0 + r) * 128 + c4);
        uint32_t* d = Abuf + r * AST + c4;
        d[0] = to_tf32(v.x); d[1] = to_tf32(v.y);
        d[2] = to_tf32(v.z); d[3] = to_tf32(v.w);
    }

    float co[4][4][4];
#pragma unroll
    for (int i = 0; i < 4; ++i)
#pragma unroll
        for (int j = 0; j < 4; ++j)
#pragma unroll
            for (int r = 0; r < 4; ++r) co[i][j][r] = 0.f;

#pragma unroll
    for (int nc = 0; nc < NC; ++nc) {
        // ============ phase 1: c1 = A @ W1[:, nc*128..] ============
        float c1[4][4][4];
#pragma unroll
        for (int i = 0; i < 4; ++i)
#pragma unroll
            for (int j = 0; j < 4; ++j)
#pragma unroll
                for (int r = 0; r < 4; ++r) c1[i][j][r] = 0.f;

        const float* Wp = W1 + nc * 128;   // rows k (stride ldw1), cols 0..127
        float4 pre0 = *(const float4*)(Wp + (size_t)k0 * ldw1 + c40);
        float4 pre1 = *(const float4*)(Wp + (size_t)k1 * ldw1 + c41);
        if (nc) __syncthreads();  // protect Bb0 from previous phase-2 kt=6 reads
        {
            uint32_t* d0 = Bb0 + o0;
            d0[0] = to_tf32(pre0.x); d0[1] = to_tf32(pre0.y);
            d0[2] = to_tf32(pre0.z); d0[3] = to_tf32(pre0.w);
            uint32_t* d1 = Bb0 + o1;
            d1[0] = to_tf32(pre1.x); d1[1] = to_tf32(pre1.y);
            d1[2] = to_tf32(pre1.z); d1[3] = to_tf32(pre1.w);
        }
        pre0 = *(const float4*)(Wp + (size_t)(16 + k0) * ldw1 + c40);
        pre1 = *(const float4*)(Wp + (size_t)(16 + k1) * ldw1 + c41);
        __syncthreads();

        for (int kt = 0; kt < 8; ++kt) {
            if (kt < 7) {
                uint32_t* stg = (kt & 1) ? Bb0 : Bb1;
                uint32_t* d0 = stg + o0;
                d0[0] = to_tf32(pre0.x); d0[1] = to_tf32(pre0.y);
                d0[2] = to_tf32(pre0.z); d0[3] = to_tf32(pre0.w);
                uint32_t* d1 = stg + o1;
                d1[0] = to_tf32(pre1.x); d1[1] = to_tf32(pre1.y);
                d1[2] = to_tf32(pre1.z); d1[3] = to_tf32(pre1.w);
                if (kt < 6) {
                    pre0 = *(const float4*)(Wp + (size_t)((kt + 2) * 16 + k0) * ldw1 + c40);
                    pre1 = *(const float4*)(Wp + (size_t)((kt + 2) * 16 + k1) * ldw1 + c41);
                }
            }
            mma_slab16_kn(Abuf, (kt & 1) ? Bb1 : Bb0, c1, wm, wn, g, tig, kt);
            if (kt < 7) __syncthreads();
        }

        // write hidden tile: relu(c1 + b1chunk) -> Tbuf (tf32)
#pragma unroll
        for (int mf = 0; mf < 4; ++mf) {
#pragma unroll
            for (int nf = 0; nf < 4; ++nf) {
                int row = wm * 64 + mf * 16 + g;
                int col = wn * 32 + nf * 8 + 2 * tig;
                float bb0 = b1[nc * 128 + col], bb1 = b1[nc * 128 + col + 1];
                Tbuf[row * AST + col]           = to_tf32(fmaxf(c1[mf][nf][0] + bb0, 0.f));
                Tbuf[row * AST + col + 1]       = to_tf32(fmaxf(c1[mf][nf][1] + bb1, 0.f));
                Tbuf[(row + 8) * AST + col]     = to_tf32(fmaxf(c1[mf][nf][2] + bb0, 0.f));
                Tbuf[(row + 8) * AST + col + 1] = to_tf32(fmaxf(c1[mf][nf][3] + bb1, 0.f));
            }
        }

        // ============ phase 2: co += T @ W2[nc*128.., :] ============
        const float* W2p = W2 + (size_t)(nc * 128) * 128;   // rows k (stride 128)
        pre0 = *(const float4*)(W2p + (size_t)k0 * 128 + c40);
        pre1 = *(const float4*)(W2p + (size_t)k1 * 128 + c41);
        __syncthreads();  // all warps past phase-1 kt=6 mma (Bb0 free)
        {
            uint32_t* d0 = Bb0 + o0;
            d0[0] = to_tf32(pre0.x); d0[1] = to_tf32(pre0.y);
            d0[2] = to_tf32(pre0.z); d0[3] = to_tf32(pre0.w);
            uint32_t* d1 = Bb0 + o1;
            d1[0] = to_tf32(pre1.x); d1[1] = to_tf32(pre1.y);
            d1[2] = to_tf32(pre1.z); d1[3] = to_tf32(pre1.w);
        }
        pre0 = *(const float4*)(W2p + (size_t)(16 + k0) * 128 + c40);
        pre1 = *(const float4*)(W2p + (size_t)(16 + k1) * 128 + c41);
        __syncthreads();  // Tbuf writes visible + Bb1 free (phase-1 kt=7 done)

        for (int kt = 0; kt < 8; ++kt) {
            if (kt < 7) {
                uint32_t* stg = (kt & 1) ? Bb0 : Bb1;
                uint32_t* d0 = stg + o0;
                d0[0] = to_tf32(pre0.x); d0[1] = to_tf32(pre0.y);
                d0[2] = to_tf32(pre0.z); d0[3] = to_tf32(pre0.w);
                uint32_t* d1 = stg + o1;
                d1[0] = to_tf32(pre1.x); d1[1] = to_tf32(pre1.y);
                d1[2] = to_tf32(pre1.z); d1[3] = to_tf32(pre1.w);
                if (kt < 6) {
                    pre0 = *(const float4*)(W2p + (size_t)((kt + 2) * 16 + k0) * 128 + c40);
                    pre1 = *(const float4*)(W2p + (size_t)((kt + 2) * 16 + k1) * 128 + c41);
                }
            }
            mma_slab16_kn(Tbuf, (kt & 1) ? Bb1 : Bb0, co, wm, wn, g, tig, kt);
            if (kt < 7) __syncthreads();
        }
    }

    gemm_epilogue<false, true, STATS>(co, b2, resid, C, 128, m0, 0,
                                      wm, wn, g, tig, tid, stats, (float*)Bb0);
}

// =====================================================================
// Flash-style BF16 attention v4: exp2-domain scores, occupancy 3.
// =====================================================================
constexpr int KP_ST = 12;
constexpr int VP_ST = 24;
constexpr int ATTN_SMEM = (512 * KP_ST + 256 * VP_ST) * 4;   // 48KB

__global__ void __launch_bounds__(256, 3)
attn_mma(const float* __restrict__ qkv, float* __restrict__ ao)
{
    extern __shared__ uint32_t sm[];
    uint32_t* Ksp = sm;
    uint32_t* Vsp = sm + 512 * KP_ST;

    const int tid  = threadIdx.x;
    const int lane = tid & 31;
    const int warp = tid >> 5;
    const int g    = lane >> 2;
    const int tig  = lane & 3;
    const int b    = blockIdx.x;
    const int gi = b >> 4, h = (b >> 1) & 7, half = b & 1;
    const float* base = qkv + (size_t)gi * SEQ * 384;
    const int m0 = half * 256 + warp * 32;
    const float QSC = 0.25f * 1.44269504f;

    for (int idx = tid; idx < 2048; idx += 256) {
        int r = idx >> 2, c4 = (idx & 3) * 4;
        float4 kv = *(const float4*)(base + (size_t)r * 384 + 128 + h * 16 + c4);
        Ksp[r * KP_ST + (c4 >> 1)]     = packbf(kv.x, kv.y);
        Ksp[r * KP_ST + (c4 >> 1) + 1] = packbf(kv.z, kv.w);
        if (idx < 1024) {
            int pr = r, dg = c4;
            float4 v0 = *(const float4*)(base + (size_t)(2 * pr)     * 384 + 256 + h * 16 + dg);
            float4 v1 = *(const float4*)(base + (size_t)(2 * pr + 1) * 384 + 256 + h * 16 + dg);
            uint32_t* vd = Vsp + pr * VP_ST + dg;
            vd[0] = packbf(v0.x, v1.x);
            vd[1] = packbf(v0.y, v1.y);
            vd[2] = packbf(v0.z, v1.z);
            vd[3] = packbf(v0.w, v1.w);
        }
    }

    uint32_t qa[2][4];
#pragma unroll
    for (int mt = 0; mt < 2; ++mt) {
        const float* qp = base + (size_t)(m0 + mt * 16 + g) * 384 + h * 16;
        float2 a0 = *(const float2*)(qp + 2 * tig);
        float2 a1 = *(const float2*)(qp + 8 * 384 + 2 * tig);
        float2 a2 = *(const float2*)(qp + 2 * tig + 8);
        float2 a3 = *(const float2*)(qp + 8 * 384 + 2 * tig + 8);
        qa[mt][0] = packbf(a0.x * QSC, a0.y * QSC);
        qa[mt][1] = packbf(a1.x * QSC, a1.y * QSC);
        qa[mt][2] = packbf(a2.x * QSC, a2.y * QSC);
        qa[mt][3] = packbf(a3.x * QSC, a3.y * QSC);
    }
    __syncthreads();

    float o[2][2][4];
    float lrow[2][2];
#pragma unroll
    for (int mt = 0; mt < 2; ++mt) {
        lrow[mt][0] = 0.f; lrow[mt][1] = 0.f;
#pragma unroll
        for (int nt = 0; nt < 2; ++nt)
#pragma unroll
            for (int r = 0; r < 4; ++r) o[mt][nt][r] = 0.f;
    }

    for (int j = 0; j < 16; ++j) {
        const int n0 = j * 32;
        uint32_t ps[2][2][4];

#pragma unroll
        for (int nt = 0; nt < 4; ++nt) {
            uint32_t bk[2];
            {
                const uint32_t* kp = Ksp + (n0 + nt * 8 + g) * KP_ST + tig;
                bk[0] = kp[0];
                bk[1] = kp[4];
            }
#pragma unroll
            for (int mt = 0; mt < 2; ++mt) {
                float c[4] = {0.f, 0.f, 0.f, 0.f};
                mma_bf16(c, qa[mt], bk);
                float p0 = fex2(c[0]);
                float p1 = fex2(c[1]);
                float p2 = fex2(c[2]);
                float p3 = fex2(c[3]);
                lrow[mt][0] += p0 + p1;
                lrow[mt][1] += p2 + p3;
                ps[mt][nt >> 1][(nt & 1) * 2 + 0] = packbf(p0, p1);
                ps[mt][nt >> 1][(nt & 1) * 2 + 1] = packbf(p2, p3);
            }
        }

#pragma unroll
        for (int c = 0; c < 2; ++c) {
            const int prb = (n0 >> 1) + c * 8;
#pragma unroll
            for (int nt = 0; nt < 2; ++nt) {
                uint32_t bv[2];
                const uint32_t* vp = Vsp + (prb + tig) * VP_ST + nt * 8 + g;
                bv[0] = vp[0];
                bv[1] = vp[4 * VP_ST];
#pragma unroll
                for (int mt = 0; mt < 2; ++mt)
                    mma_bf16(o[mt][nt], ps[mt][c], bv);
            }
        }
    }

#pragma unroll
    for (int mt = 0; mt < 2; ++mt) {
        float l0 = lrow[mt][0], l1 = lrow[mt][1];
        l0 += __shfl_xor_sync(0xffffffffu, l0, 1);
        l0 += __shfl_xor_sync(0xffffffffu, l0, 2);
        l1 += __shfl_xor_sync(0xffffffffu, l1, 1);
        l1 += __shfl_xor_sync(0xffffffffu, l1, 2);
        float i0 = 1.f / l0, i1 = 1.f / l1;
        int grow = gi * SEQ + m0 + mt * 16 + g;
#pragma unroll
        for (int nt = 0; nt < 2; ++nt) {
            int col = h * 16 + nt * 8 + 2 * tig;
            *(float2*)(ao + (size_t)grow * DD + col) =
                make_float2(o[mt][nt][0] * i0, o[mt][nt][1] * i0);
            *(float2*)(ao + (size_t)(grow + 8) * DD + col) =
                make_float2(o[mt][nt][2] * i1, o[mt][nt][3] * i1);
        }
    }
}

// =====================================================================
// BatchNorm applies
// =====================================================================
__device__ __forceinline__ void bn_coef(const float* stats, const float* gamma,
                                        const float* beta, int col,
                                        float& sc, float& sh)
{
    float mean = stats[col] * (1.f / (float)NN);
    float var  = stats[128 + col] * (1.f / (float)NN) - mean * mean;
    sc = gamma[col] * rsqrtf(var + 1e-5f);
    sh = beta[col] - mean * sc;
}

__global__ void __launch_bounds__(256)
bn_apply_one(const float* __restrict__ X, const float* __restrict__ stats,
             const float* __restrict__ gamma, const float* __restrict__ beta,
             float* __restrict__ out)
{
    int col = threadIdx.x & 127;
    int half = threadIdx.x >> 7;
    float sc, sh;
    bn_coef(stats, gamma, beta, col, sc, sh);
    int row0 = blockIdx.x * 128 + half * 64;
    size_t off = (size_t)row0 * DD + col;
#pragma unroll 4
    for (int r = 0; r < 64; ++r)
        out[off + r * DD] = X[off + r * DD] * sc + sh;
}

__global__ void __launch_bounds__(256)
bn_apply_dual(const float* __restrict__ ha, const float* __restrict__ statsA,
              const float* __restrict__ ga, const float* __restrict__ ba,
              const float* __restrict__ hl, const float* __restrict__ statsL,
              const float* __restrict__ gl, const float* __restrict__ bl,
              float* __restrict__ out)
{
    int col = threadIdx.x & 127;
    int half = threadIdx.x >> 7;
    float scA, shA, scL, shL;
    bn_coef(statsA, ga, ba, col, scA, shA);
    bn_coef(statsL, gl, bl, col, scL, shL);
    int row0 = blockIdx.x * 128 + half * 64;
    size_t off = (size_t)row0 * DD + col;
#pragma unroll 4
    for (int r = 0; r < 64; ++r)
        out[off + r * DD] = ha[off + r * DD] * scA + shA
                          + hl[off + r * DD] * scL + shL;
}

// =====================================================================
// Host launcher — two-stream fork/join captured as a branching graph.
// =====================================================================
extern "C" void kernel_launch(void* const* d_in, const int* in_sizes, int n_in,
                              void* d_out, int out_size)
{
    const float* x          = (const float*)d_in[0];
    const int*   edge_index = (const int*)  d_in[1];
    const float* edge_attr  = (const float*)d_in[2];
    const float* gin_w1     = (const float*)d_in[3];
    const float* gin_b1     = (const float*)d_in[4];
    const float* gin_w2     = (const float*)d_in[5];
    const float* gin_b2     = (const float*)d_in[6];
    const float* bn1l_g     = (const float*)d_in[7];
    const float* bn1l_b     = (const float*)d_in[8];
    const float* in_proj_w  = (const float*)d_in[9];
    const float* in_proj_b  = (const float*)d_in[10];
    const float* out_proj_w = (const float*)d_in[11];
    const float* out_proj_b = (const float*)d_in[12];
    const float* bn1a_g     = (const float*)d_in[13];
    const float* bn1a_b     = (const float*)d_in[14];
    const float* ff_w1      = (const float*)d_in[15];
    const float* ff_b1      = (const float*)d_in[16];
    const float* ff_w2      = (const float*)d_in[17];
    const float* ff_b2      = (const float*)d_in[18];
    const float* bn2_g      = (const float*)d_in[19];
    const float* bn2_b      = (const float*)d_in[20];
    float* out = (float*)d_out;

    static cudaStream_t sB = nullptr;
    static cudaEvent_t evFork = nullptr, evJoin = nullptr;
    if (sB == nullptr) {
        cudaStreamCreateWithFlags(&sB, cudaStreamNonBlocking);
        cudaEventCreateWithFlags(&evFork, cudaEventDisableTiming);
        cudaEventCreateWithFlags(&evJoin, cudaEventDisableTiming);
        cudaFuncSetAttribute(attn_mma, cudaFuncAttributeMaxDynamicSharedMemorySize, ATTN_SMEM);
        cudaFuncSetAttribute(gemm_ar<false, false>, cudaFuncAttributeMaxDynamicSharedMemorySize, GEMM_AR_SMEM);
        cudaFuncSetAttribute(gemm_ar<true,  true >, cudaFuncAttributeMaxDynamicSharedMemorySize, GEMM_AR_SMEM);
        cudaFuncSetAttribute(mlp_fused<1, true>, cudaFuncAttributeMaxDynamicSharedMemorySize, MLP_SMEM);
        cudaFuncSetAttribute(mlp_fused<2, true>, cudaFuncAttributeMaxDynamicSharedMemorySize, MLP_SMEM);
    }

    float *z, *hl, *qkvb, *ao, *ha, *h, *h2, *stats;
    int *deg, *off, *pos, *eid;
    cudaGetSymbolAddress((void**)&z,    g_z);
    cudaGetSymbolAddress((void**)&hl,   g_hl);
    cudaGetSymbolAddress((void**)&qkvb, g_qkv);
    cudaGetSymbolAddress((void**)&ao,   g_ao);
    cudaGetSymbolAddress((void**)&ha,   g_ha);
    cudaGetSymbolAddress((void**)&h,    g_h);
    cudaGetSymbolAddress((void**)&h2,   g_h2);
    cudaGetSymbolAddress((void**)&stats, g_stats);
    cudaGetSymbolAddress((void**)&deg,  g_deg);
    cudaGetSymbolAddress((void**)&off,  g_off);
    cudaGetSymbolAddress((void**)&pos,  g_pos);
    cudaGetSymbolAddress((void**)&eid,  g_eid);

    const int* src = edge_index;
    const int* dst = edge_index + EE;
    const dim3 blk(256);
    const int GB = NN / 128;

    float* stats_hl = stats;
    float* stats_ha = stats + 256;
    float* stats_h2 = stats + 512;

    // ---- common prologue on null stream ----
    zero_misc<<<64, blk>>>(deg, stats);                                            // 0

    // ---- fork: stream B = attention branch ----
    cudaEventRecord(evFork, 0);
    cudaStreamWaitEvent(sB, evFork, 0);

    gemm_ar<false, false><<<dim3(GB, 3), blk, GEMM_AR_SMEM, sB>>>(
        x, in_proj_w, in_proj_b, nullptr, qkvb, 384, nullptr);                     // 1 (B)
    count_kernel<<<EE / 256, blk>>>(dst, deg);                                     // 2 (A)
    attn_mma<<<NGR * NH * 2, blk, ATTN_SMEM, sB>>>(qkvb, ao);                      // 3 (B) <- profiled
    scan_kernel<<<1, 1024>>>(deg, off, pos);                                       // 4 (A)
    scatter_kernel<<<EE / 256, blk>>>(dst, pos, eid);                              // 5 (A)
    gemm_ar<true, true><<<dim3(GB, 1), blk, GEMM_AR_SMEM, sB>>>(
        ao, out_proj_w, out_proj_b, x, ha, 128, stats_ha);                         // 6 (B)
    aggr_kernel<<<NN / 8, blk>>>(x, src, edge_attr, off, eid, z);                  // 7 (A)
    mlp_fused<1, true><<<GB, blk, MLP_SMEM>>>(z, gin_w1, gin_b1, gin_w2, gin_b2,
                                              x, hl, stats_hl);                    // 8 (A)

    // ---- join ----
    cudaEventRecord(evJoin, sB);
    cudaStreamWaitEvent(0, evJoin, 0);

    bn_apply_dual<<<128, blk>>>(ha, stats_ha, bn1a_g, bn1a_b,
                                hl, stats_hl, bn1l_g, bn1l_b, h);                  // 9
    mlp_fused<2, true><<<GB, blk, MLP_SMEM>>>(h, ff_w1, ff_b1, ff_w2, ff_b2,
                                              h, h2, stats_h2);                    // 10
    bn_apply_one<<<128, blk>>>(h2, stats_h2, bn2_g, bn2_b, out);                   // 11
}

// round 14
// speedup vs baseline: 1.0943x; 1.0156x over previous
#include <cuda_runtime.h>
#include <cuda_bf16.h>
#include <math.h>
#include <stdint.h>

// Problem constants
constexpr int NN  = 16384;   // nodes
constexpr int DD  = 128;     // dim
constexpr int EE  = 262144;  // edges
constexpr int SEQ = 512;     // nodes per graph
constexpr int NGR = 32;      // graphs
constexpr int NH  = 8;       // heads (dh = 16)

// ---------------- scratch ----------------
__device__ float g_z   [NN * DD];
__device__ float g_hl  [NN * DD];
__device__ float g_qkv [NN * 3 * DD];
__device__ float g_ao  [NN * DD];
__device__ float g_ha  [NN * DD];
__device__ float g_h2  [NN * DD];
__device__ float g_stats[768];
__device__ int   g_deg [NN];
__device__ int   g_off [NN + 1];
__device__ int   g_pos [NN];
__device__ int   g_eid [EE];

// =====================================================================
__global__ void zero_misc(int* deg, float* stats)
{
    int i = blockIdx.x * 256 + threadIdx.x;
    deg[i] = 0;
    if (i < 768) stats[i] = 0.f;
}

// =====================================================================
// CSR build by dst:  count -> scan -> scatter
// =====================================================================
__global__ void count_kernel(const int* __restrict__ dst, int* __restrict__ deg)
{
    int e = blockIdx.x * 256 + threadIdx.x;
    atomicAdd(&deg[dst[e]], 1);
}

__global__ void __launch_bounds__(1024)
scan_kernel(const int* __restrict__ deg, int* __restrict__ off, int* __restrict__ pos)
{
    __shared__ int buf[2][1024];
    int t = threadIdx.x;
    int base = t * 16;
    int loc[16];
    int sum = 0;
#pragma unroll
    for (int i = 0; i < 16; ++i) { loc[i] = sum; sum += deg[base + i]; }
    buf[0][t] = sum;
    __syncthreads();
    int sel = 0;
    for (int d = 1; d < 1024; d <<= 1) {
        int v = buf[sel][t] + (t >= d ? buf[sel][t - d] : 0);
        buf[sel ^ 1][t] = v;
        sel ^= 1;
        __syncthreads();
    }
    int excl = buf[sel][t] - sum;
#pragma unroll
    for (int i = 0; i < 16; ++i) {
        int o = excl + loc[i];
        off[base + i] = o;
        pos[base + i] = o;
    }
    if (t == 1023) off[NN] = excl + sum;
}

__global__ void scatter_kernel(const int* __restrict__ dst, int* __restrict__ pos,
                               int* __restrict__ eid)
{
    int e = blockIdx.x * 256 + threadIdx.x;
    int p = atomicAdd(&pos[dst[e]], 1);
    eid[p] = e;
}

// =====================================================================
// Gather aggregation: z = x + sum_{e -> node} relu(x[src[e]] + ea[e])
// =====================================================================
__global__ void __launch_bounds__(256)
aggr_kernel(const float* __restrict__ x, const int* __restrict__ src,
            const float* __restrict__ ea, const int* __restrict__ off,
            const int* __restrict__ eid, float* __restrict__ z)
{
    int node = blockIdx.x * 8 + (threadIdx.x >> 5);
    int lane = threadIdx.x & 31;
    int beg = off[node], end = off[node + 1];
    const float4* x4  = (const float4*)x;
    const float4* ea4 = (const float4*)ea;
    float4 acc = make_float4(0.f, 0.f, 0.f, 0.f);
#pragma unroll 2
    for (int i = beg; i < end; ++i) {
        int e = __ldg(eid + i);
        int s = __ldg(src + e);
        float4 a = x4[(size_t)s * 32 + lane];
        float4 b = ea4[(size_t)e * 32 + lane];
        acc.x += fmaxf(a.x + b.x, 0.f);
        acc.y += fmaxf(a.y + b.y, 0.f);
        acc.z += fmaxf(a.z + b.z, 0.f);
        acc.w += fmaxf(a.w + b.w, 0.f);
    }
    float4 xv = x4[(size_t)node * 32 + lane];
    ((float4*)z)[(size_t)node * 32 + lane] =
        make_float4(xv.x + acc.x, xv.y + acc.y, xv.z + acc.z, xv.w + acc.w);
}

// =====================================================================
// mma helpers
// =====================================================================
__device__ __forceinline__ uint32_t to_tf32(float f)
{
    uint32_t u;
    asm("cvt.rna.tf32.f32 %0, %1;" : "=r"(u) : "f"(f));
    return u;
}

__device__ __forceinline__ void mma_tf32(float c[4], const uint32_t a[4], const uint32_t b[2])
{
    asm volatile(
        "mma.sync.aligned.m16n8k8.row.col.f32.tf32.tf32.f32 "
        "{%0,%1,%2,%3}, {%4,%5,%6,%7}, {%8,%9}, {%0,%1,%2,%3};\n"
        : "+f"(c[0]), "+f"(c[1]), "+f"(c[2]), "+f"(c[3])
        : "r"(a[0]), "r"(a[1]), "r"(a[2]), "r"(a[3]), "r"(b[0]), "r"(b[1]));
}

__device__ __forceinline__ void mma_bf16(float c[4], const uint32_t a[4], const uint32_t b[2])
{
    asm volatile(
        "mma.sync.aligned.m16n8k16.row.col.f32.bf16.bf16.f32 "
        "{%0,%1,%2,%3}, {%4,%5,%6,%7}, {%8,%9}, {%0,%1,%2,%3};\n"
        : "+f"(c[0]), "+f"(c[1]), "+f"(c[2]), "+f"(c[3])
        : "r"(a[0]), "r"(a[1]), "r"(a[2]), "r"(a[3]), "r"(b[0]), "r"(b[1]));
}

__device__ __forceinline__ uint32_t packbf(float lo, float hi)
{
    uint32_t r;
    asm("cvt.rn.bf16x2.f32 %0, %1, %2;" : "=r"(r) : "f"(hi), "f"(lo));
    return r;
}

__device__ __forceinline__ float fex2(float x)
{
    float y;
    asm("ex2.approx.f32 %0, %1;" : "=f"(y) : "f"(x));
    return y;
}

constexpr int AST  = 132;   // A/T smem stride (u32)
constexpr int BST  = 20;    // [n][k] B-chunk stride (gemm_ar)
constexpr int BSTK = 132;   // [k][n] B-chunk stride (mlp_fused)

// one 16-k-slab: A-src (stride AST), B-chunk [n][k] (stride BST)
__device__ __forceinline__ void mma_slab16(const uint32_t* S, const uint32_t* Bb,
                                           float acc[4][4][4],
                                           int wm, int wn, int g, int tig, int kt)
{
#pragma unroll
    for (int k8s = 0; k8s < 2; ++k8s) {
        const int kk = kt * 16 + k8s * 8;
        uint32_t af[4][4];
#pragma unroll
        for (int mf = 0; mf < 4; ++mf) {
            const uint32_t* pa = S + (wm * 64 + mf * 16 + g) * AST + kk + tig;
            af[mf][0] = pa[0];
            af[mf][1] = pa[8 * AST];
            af[mf][2] = pa[4];
            af[mf][3] = pa[8 * AST + 4];
        }
        uint32_t bf[4][2];
#pragma unroll
        for (int nf = 0; nf < 4; ++nf) {
            const uint32_t* pb = Bb + (wn * 32 + nf * 8 + g) * BST + k8s * 8 + tig;
            bf[nf][0] = pb[0];
            bf[nf][1] = pb[4];
        }
#pragma unroll
        for (int mf = 0; mf < 4; ++mf)
#pragma unroll
            for (int nf = 0; nf < 4; ++nf)
                mma_tf32(acc[mf][nf], af[mf], bf[nf]);
    }
}

// one 16-k-slab: A-src (stride AST), B-chunk [k][n] (stride BSTK; 16 rows)
__device__ __forceinline__ void mma_slab16_kn(const uint32_t* S, const uint32_t* Bkn,
                                              float acc[4][4][4],
                                              int wm, int wn, int g, int tig, int kt)
{
#pragma unroll
    for (int k8s = 0; k8s < 2; ++k8s) {
        const int kk = kt * 16 + k8s * 8;
        uint32_t af[4][4];
#pragma unroll
        for (int mf = 0; mf < 4; ++mf) {
            const uint32_t* pa = S + (wm * 64 + mf * 16 + g) * AST + kk + tig;
            af[mf][0] = pa[0];
            af[mf][1] = pa[8 * AST];
            af[mf][2] = pa[4];
            af[mf][3] = pa[8 * AST + 4];
        }
        uint32_t bf[4][2];
        const uint32_t* pb0 = Bkn + (k8s * 8 + tig) * BSTK;
        const uint32_t* pb1 = pb0 + 4 * BSTK;
#pragma unroll
        for (int nf = 0; nf < 4; ++nf) {
            int n = wn * 32 + nf * 8 + g;
            bf[nf][0] = pb0[n];
            bf[nf][1] = pb1[n];
        }
#pragma unroll
        for (int mf = 0; mf < 4; ++mf)
#pragma unroll
            for (int nf = 0; nf < 4; ++nf)
                mma_tf32(acc[mf][nf], af[mf], bf[nf]);
    }
}

// epilogue shared by gemm_ar / mlp_fused (MF=4)
// BNRES: residual recomputed as bnA(haP)+bnL(hlP) using smem coef[512].
template<bool RELU, bool RESID, bool STATS, bool BNRES>
__device__ __forceinline__ void gemm_epilogue(
    float acc[4][4][4], const float* bias, const float* resid,
    float* C, int ldc, int m0, int n0,
    int wm, int wn, int g, int tig, int tid,
    float* stats, float* sst,
    const float* haP, const float* hlP, const float* coef)
{
    float cs[8], cq[8];
    if (STATS) {
#pragma unroll
        for (int j = 0; j < 8; ++j) { cs[j] = 0.f; cq[j] = 0.f; }
    }
#pragma unroll
    for (int mf = 0; mf < 4; ++mf) {
#pragma unroll
        for (int nf = 0; nf < 4; ++nf) {
            int row = m0 + wm * 64 + mf * 16 + g;
            int col = n0 + wn * 32 + nf * 8 + 2 * tig;
            float b0 = bias[col], b1 = bias[col + 1];
            float o00 = acc[mf][nf][0] + b0, o01 = acc[mf][nf][1] + b1;
            float o10 = acc[mf][nf][2] + b0, o11 = acc[mf][nf][3] + b1;
            if (RELU) {
                o00 = fmaxf(o00, 0.f); o01 = fmaxf(o01, 0.f);
                o10 = fmaxf(o10, 0.f); o11 = fmaxf(o11, 0.f);
            }
            if (RESID) {
                float2 r0, r1;
                if (BNRES) {
                    float sA0 = coef[col],       hA0 = coef[128 + col];
                    float sA1 = coef[col + 1],   hA1 = coef[128 + col + 1];
                    float sL0 = coef[256 + col], hL0 = coef[384 + col];
                    float sL1 = coef[256 + col + 1], hL1 = coef[384 + col + 1];
                    float2 a0 = *(const float2*)(haP + (size_t)row * ldc + col);
                    float2 a1 = *(const float2*)(haP + (size_t)(row + 8) * ldc + col);
                    float2 l0 = *(const float2*)(hlP + (size_t)row * ldc + col);
                    float2 l1 = *(const float2*)(hlP + (size_t)(row + 8) * ldc + col);
                    r0.x = a0.x * sA0 + hA0 + l0.x * sL0 + hL0;
                    r0.y = a0.y * sA1 + hA1 + l0.y * sL1 + hL1;
                    r1.x = a1.x * sA0 + hA0 + l1.x * sL0 + hL0;
                    r1.y = a1.y * sA1 + hA1 + l1.y * sL1 + hL1;
                } else {
                    r0 = *(const float2*)(resid + (size_t)row * ldc + col);
                    r1 = *(const float2*)(resid + (size_t)(row + 8) * ldc + col);
                }
                o00 += r0.x; o01 += r0.y;
                o10 += r1.x; o11 += r1.y;
            }
            if (STATS) {
                cs[nf*2]   += o00 + o10;
                cs[nf*2+1] += o01 + o11;
                cq[nf*2]   += o00*o00 + o10*o10;
                cq[nf*2+1] += o01*o01 + o11*o11;
            }
            *(float2*)(C + (size_t)row * ldc + col)       = make_float2(o00, o01);
            *(float2*)(C + (size_t)(row + 8) * ldc + col) = make_float2(o10, o11);
        }
    }
    if (STATS) {
        __syncthreads();
        sst[tid] = 0.f;
        __syncthreads();
#pragma unroll
        for (int j = 0; j < 8; ++j) {
            int col = wn * 32 + (j >> 1) * 8 + 2 * tig + (j & 1);
            atomicAdd(&sst[col],       cs[j]);
            atomicAdd(&sst[128 + col], cq[j]);
        }
        __syncthreads();
        atomicAdd(&stats[tid], sst[tid]);
    }
}

// BN coefficient helper
__device__ __forceinline__ void bn_coef(const float* stats, const float* gamma,
                                        const float* beta, int col,
                                        float& sc, float& sh)
{
    float mean = stats[col] * (1.f / (float)NN);
    float var  = stats[128 + col] * (1.f / (float)NN) - mean * mean;
    sc = gamma[col] * rsqrtf(var + 1e-5f);
    sh = beta[col] - mean * sc;
}

// =====================================================================
// A-resident GEMM (K=128): C = A[128rows,128] @ B^T + bias (+resid)(+stats)
// =====================================================================
constexpr int GEMM_AR_SMEM = (128 * AST + 2 * 128 * BST) * 4;

template<bool RESID, bool STATS>
__global__ void __launch_bounds__(256, 2)
gemm_ar(const float* __restrict__ A,
        const float* __restrict__ B,
        const float* __restrict__ bias,
        const float* __restrict__ resid,
        float* __restrict__ C, int ldc,
        float* __restrict__ stats)
{
    extern __shared__ uint32_t sm[];
    uint32_t* Abuf = sm;
    uint32_t* Bb0  = sm + 128 * AST;
    uint32_t* Bb1  = Bb0 + 128 * BST;

    const int tid = threadIdx.x;
    const int lane = tid & 31, warp = tid >> 5;
    const int wm = warp >> 2, wn = warp & 3;
    const int g = lane >> 2, tig = lane & 3;
    const int m0 = blockIdx.x * 128;
    const int n0 = blockIdx.y * 128;
    const int i0 = tid, i1 = tid + 256;
    const float* Bp0 = B + (size_t)(n0 + (i0 >> 2)) * 128 + (i0 & 3) * 4;
    const float* Bp1 = B + (size_t)(n0 + (i1 >> 2)) * 128 + (i1 & 3) * 4;
    const int o0 = (i0 >> 2) * BST + (i0 & 3) * 4;
    const int o1 = (i1 >> 2) * BST + (i1 & 3) * 4;

#pragma unroll
    for (int it = 0; it < 16; ++it) {
        int idx = tid + it * 256;
        int r = idx >> 5, c4 = (idx & 31) * 4;
        float4 v = *(const float4*)(A + (size_t)(m0 + r) * 128 + c4);
        uint32_t* d = Abuf + r * AST + c4;
        d[0] = to_tf32(v.x); d[1] = to_tf32(v.y);
        d[2] = to_tf32(v.z); d[3] = to_tf32(v.w);
    }

    float acc[4][4][4];
#pragma unroll
    for (int i = 0; i < 4; ++i)
#pragma unroll
        for (int j = 0; j < 4; ++j)
#pragma unroll
            for (int r = 0; r < 4; ++r) acc[i][j][r] = 0.f;

    float4 pre0 = *(const float4*)(Bp0);
    float4 pre1 = *(const float4*)(Bp1);
    {
        uint32_t* d0 = Bb0 + o0;
        d0[0] = to_tf32(pre0.x); d0[1] = to_tf32(pre0.y);
        d0[2] = to_tf32(pre0.z); d0[3] = to_tf32(pre0.w);
        uint32_t* d1 = Bb0 + o1;
        d1[0] = to_tf32(pre1.x); d1[1] = to_tf32(pre1.y);
        d1[2] = to_tf32(pre1.z); d1[3] = to_tf32(pre1.w);
    }
    pre0 = *(const float4*)(Bp0 + 16);
    pre1 = *(const float4*)(Bp1 + 16);
    __syncthreads();

    for (int kt = 0; kt < 8; ++kt) {
        if (kt < 7) {
            uint32_t* stg = (kt & 1) ? Bb0 : Bb1;
            uint32_t* d0 = stg + o0;
            d0[0] = to_tf32(pre0.x); d0[1] = to_tf32(pre0.y);
            d0[2] = to_tf32(pre0.z); d0[3] = to_tf32(pre0.w);
            uint32_t* d1 = stg + o1;
            d1[0] = to_tf32(pre1.x); d1[1] = to_tf32(pre1.y);
            d1[2] = to_tf32(pre1.z); d1[3] = to_tf32(pre1.w);
            if (kt < 6) {
                pre0 = *(const float4*)(Bp0 + (kt + 2) * 16);
                pre1 = *(const float4*)(Bp1 + (kt + 2) * 16);
            }
        }
        mma_slab16(Abuf, (kt & 1) ? Bb1 : Bb0, acc, wm, wn, g, tig, kt);
        if (kt < 7) __syncthreads();
    }

    gemm_epilogue<false, RESID, STATS, false>(acc, bias, resid, C, ldc, m0, n0,
                                              wm, wn, g, tig, tid, stats, (float*)Bb0,
                                              nullptr, nullptr, nullptr);
}

// =====================================================================
// Fused MLP: C = relu(A' @ W1 + b1) @ W2 + b2 + resid' (+stats)
// BNIN: A' = bnA(A=ha) + bnL(resid=hl) computed inline (== bn_apply_dual);
//       residual recomputed the same way in the epilogue.
// Coalesced [k][n] weight staging, double-buffered, 1 sync/chunk.
// =====================================================================
constexpr int MLP_SMEM = (2 * 128 * AST + 2 * 16 * BSTK) * 4;   // ~152KB

template<int NC, bool STATS, bool BNIN>
__global__ void __launch_bounds__(256, 1)
mlp_fused(const float* __restrict__ A,
          const float* __restrict__ W1, const float* __restrict__ b1,
          const float* __restrict__ W2, const float* __restrict__ b2,
          const float* __restrict__ resid,
          float* __restrict__ C,
          float* __restrict__ stats,
          const float* __restrict__ stA, const float* __restrict__ gA,
          const float* __restrict__ bA,
          const float* __restrict__ stL, const float* __restrict__ gL,
          const float* __restrict__ bL)
{
    extern __shared__ uint32_t sm[];
    uint32_t* Abuf = sm;                   // [128][AST]
    uint32_t* Tbuf = sm + 128 * AST;       // [128][AST]
    uint32_t* Bb0  = sm + 2 * 128 * AST;   // [16][BSTK] stage 0
    uint32_t* Bb1  = Bb0 + 16 * BSTK;      // [16][BSTK] stage 1
    __shared__ float coef[512];            // scA, shA, scL, shL

    const int tid = threadIdx.x;
    const int lane = tid & 31, warp = tid >> 5;
    const int wm = warp >> 2, wn = warp & 3;
    const int g = lane >> 2, tig = lane & 3;
    const int m0 = blockIdx.x * 128;
    const int ldw1 = NC * 128;

    const int i0 = tid, i1 = tid + 256;
    const int k0 = i0 >> 5, c40 = (i0 & 31) * 4;
    const int k1 = i1 >> 5, c41 = (i1 & 31) * 4;
    const int o0 = k0 * BSTK + c40;
    const int o1 = k1 * BSTK + c41;

    if (BNIN) {
        if (tid < 128) {
            float sc, sh;
            bn_coef(stA, gA, bA, tid, sc, sh);
            coef[tid] = sc; coef[128 + tid] = sh;
            bn_coef(stL, gL, bL, tid, sc, sh);
            coef[256 + tid] = sc; coef[384 + tid] = sh;
        }
        __syncthreads();
    }

#pragma unroll
    for (int it = 0; it < 16; ++it) {
        int idx = tid + it * 256;
        int r = idx >> 5, c4 = (idx & 31) * 4;
        float4 v = *(const float4*)(A + (size_t)(m0 + r) * 128 + c4);
        if (BNIN) {
            float4 w = *(const float4*)(resid + (size_t)(m0 + r) * 128 + c4);
            v.x = v.x * coef[c4]     + coef[128 + c4]     + w.x * coef[256 + c4]     + coef[384 + c4];
            v.y = v.y * coef[c4 + 1] + coef[128 + c4 + 1] + w.y * coef[256 + c4 + 1] + coef[384 + c4 + 1];
            v.z = v.z * coef[c4 + 2] + coef[128 + c4 + 2] + w.z * coef[256 + c4 + 2] + coef[384 + c4 + 2];
            v.w = v.w * coef[c4 + 3] + coef[128 + c4 + 3] + w.w * coef[256 + c4 + 3] + coef[384 + c4 + 3];
        }
        uint32_t* d = Abuf + r * AST + c4;
        d[0] = to_tf32(v.x); d[1] = to_tf32(v.y);
        d[2] = to_tf32(v.z); d[3] = to_tf32(v.w);
    }

    float co[4][4][4];
#pragma unroll
    for (int i = 0; i < 4; ++i)
#pragma unroll
        for (int j = 0; j < 4; ++j)
#pragma unroll
            for (int r = 0; r < 4; ++r) co[i][j][r] = 0.f;

#pragma unroll
    for (int nc = 0; nc < NC; ++nc) {
        // ============ phase 1: c1 = A' @ W1[:, nc*128..] ============
        float c1[4][4][4];
#pragma unroll
        for (int i = 0; i < 4; ++i)
#pragma unroll
            for (int j = 0; j < 4; ++j)
#pragma unroll
                for (int r = 0; r < 4; ++r) c1[i][j][r] = 0.f;

        const float* Wp = W1 + nc * 128;
        float4 pre0 = *(const float4*)(Wp + (size_t)k0 * ldw1 + c40);
        float4 pre1 = *(const float4*)(Wp + (size_t)k1 * ldw1 + c41);
        if (nc) __syncthreads();
        {
            uint32_t* d0 = Bb0 + o0;
            d0[0] = to_tf32(pre0.x); d0[1] = to_tf32(pre0.y);
            d0[2] = to_tf32(pre0.z); d0[3] = to_tf32(pre0.w);
            uint32_t* d1 = Bb0 + o1;
            d1[0] = to_tf32(pre1.x); d1[1] = to_tf32(pre1.y);
            d1[2] = to_tf32(pre1.z); d1[3] = to_tf32(pre1.w);
        }
        pre0 = *(const float4*)(Wp + (size_t)(16 + k0) * ldw1 + c40);
        pre1 = *(const float4*)(Wp + (size_t)(16 + k1) * ldw1 + c41);
        __syncthreads();

        for (int kt = 0; kt < 8; ++kt) {
            if (kt < 7) {
                uint32_t* stg = (kt & 1) ? Bb0 : Bb1;
                uint32_t* d0 = stg + o0;
                d0[0] = to_tf32(pre0.x); d0[1] = to_tf32(pre0.y);
                d0[2] = to_tf32(pre0.z); d0[3] = to_tf32(pre0.w);
                uint32_t* d1 = stg + o1;
                d1[0] = to_tf32(pre1.x); d1[1] = to_tf32(pre1.y);
                d1[2] = to_tf32(pre1.z); d1[3] = to_tf32(pre1.w);
                if (kt < 6) {
                    pre0 = *(const float4*)(Wp + (size_t)((kt + 2) * 16 + k0) * ldw1 + c40);
                    pre1 = *(const float4*)(Wp + (size_t)((kt + 2) * 16 + k1) * ldw1 + c41);
                }
            }
            mma_slab16_kn(Abuf, (kt & 1) ? Bb1 : Bb0, c1, wm, wn, g, tig, kt);
            if (kt < 7) __syncthreads();
        }

        // write hidden tile: relu(c1 + b1chunk) -> Tbuf (tf32)
#pragma unroll
        for (int mf = 0; mf < 4; ++mf) {
#pragma unroll
            for (int nf = 0; nf < 4; ++nf) {
                int row = wm * 64 + mf * 16 + g;
                int col = wn * 32 + nf * 8 + 2 * tig;
                float bb0 = b1[nc * 128 + col], bb1 = b1[nc * 128 + col + 1];
                Tbuf[row * AST + col]           = to_tf32(fmaxf(c1[mf][nf][0] + bb0, 0.f));
                Tbuf[row * AST + col + 1]       = to_tf32(fmaxf(c1[mf][nf][1] + bb1, 0.f));
                Tbuf[(row + 8) * AST + col]     = to_tf32(fmaxf(c1[mf][nf][2] + bb0, 0.f));
                Tbuf[(row + 8) * AST + col + 1] = to_tf32(fmaxf(c1[mf][nf][3] + bb1, 0.f));
            }
        }

        // ============ phase 2: co += T @ W2[nc*128.., :] ============
        const float* W2p = W2 + (size_t)(nc * 128) * 128;
        pre0 = *(const float4*)(W2p + (size_t)k0 * 128 + c40);
        pre1 = *(const float4*)(W2p + (size_t)k1 * 128 + c41);
        __syncthreads();
        {
            uint32_t* d0 = Bb0 + o0;
            d0[0] = to_tf32(pre0.x); d0[1] = to_tf32(pre0.y);
            d0[2] = to_tf32(pre0.z); d0[3] = to_tf32(pre0.w);
            uint32_t* d1 = Bb0 + o1;
            d1[0] = to_tf32(pre1.x); d1[1] = to_tf32(pre1.y);
            d1[2] = to_tf32(pre1.z); d1[3] = to_tf32(pre1.w);
        }
        pre0 = *(const float4*)(W2p + (size_t)(16 + k0) * 128 + c40);
        pre1 = *(const float4*)(W2p + (size_t)(16 + k1) * 128 + c41);
        __syncthreads();

        for (int kt = 0; kt < 8; ++kt) {
            if (kt < 7) {
                uint32_t* stg = (kt & 1) ? Bb0 : Bb1;
                uint32_t* d0 = stg + o0;
                d0[0] = to_tf32(pre0.x); d0[1] = to_tf32(pre0.y);
                d0[2] = to_tf32(pre0.z); d0[3] = to_tf32(pre0.w);
                uint32_t* d1 = stg + o1;
                d1[0] = to_tf32(pre1.x); d1[1] = to_tf32(pre1.y);
                d1[2] = to_tf32(pre1.z); d1[3] = to_tf32(pre1.w);
                if (kt < 6) {
                    pre0 = *(const float4*)(W2p + (size_t)((kt + 2) * 16 + k0) * 128 + c40);
                    pre1 = *(const float4*)(W2p + (size_t)((kt + 2) * 16 + k1) * 128 + c41);
                }
            }
            mma_slab16_kn(Tbuf, (kt & 1) ? Bb1 : Bb0, co, wm, wn, g, tig, kt);
            if (kt < 7) __syncthreads();
        }
    }

    gemm_epilogue<false, true, STATS, BNIN>(co, b2, resid, C, 128, m0, 0,
                                            wm, wn, g, tig, tid, stats, (float*)Bb0,
                                            A, resid, coef);
}

// =====================================================================
// Flash-style BF16 attention v4: exp2-domain scores, occupancy 3.
// =====================================================================
constexpr int KP_ST = 12;
constexpr int VP_ST = 24;
constexpr int ATTN_SMEM = (512 * KP_ST + 256 * VP_ST) * 4;   // 48KB

__global__ void __launch_bounds__(256, 3)
attn_mma(const float* __restrict__ qkv, float* __restrict__ ao)
{
    extern __shared__ uint32_t sm[];
    uint32_t* Ksp = sm;
    uint32_t* Vsp = sm + 512 * KP_ST;

    const int tid  = threadIdx.x;
    const int lane = tid & 31;
    const int warp = tid >> 5;
    const int g    = lane >> 2;
    const int tig  = lane & 3;
    const int b    = blockIdx.x;
    const int gi = b >> 4, h = (b >> 1) & 7, half = b & 1;
    const float* base = qkv + (size_t)gi * SEQ * 384;
    const int m0 = half * 256 + warp * 32;
    const float QSC = 0.25f * 1.44269504f;

    for (int idx = tid; idx < 2048; idx += 256) {
        int r = idx >> 2, c4 = (idx & 3) * 4;
        float4 kv = *(const float4*)(base + (size_t)r * 384 + 128 + h * 16 + c4);
        Ksp[r * KP_ST + (c4 >> 1)]     = packbf(kv.x, kv.y);
        Ksp[r * KP_ST + (c4 >> 1) + 1] = packbf(kv.z, kv.w);
        if (idx < 1024) {
            int pr = r, dg = c4;
            float4 v0 = *(const float4*)(base + (size_t)(2 * pr)     * 384 + 256 + h * 16 + dg);
            float4 v1 = *(const float4*)(base + (size_t)(2 * pr + 1) * 384 + 256 + h * 16 + dg);
            uint32_t* vd = Vsp + pr * VP_ST + dg;
            vd[0] = packbf(v0.x, v1.x);
            vd[1] = packbf(v0.y, v1.y);
            vd[2] = packbf(v0.z, v1.z);
            vd[3] = packbf(v0.w, v1.w);
        }
    }

    uint32_t qa[2][4];
#pragma unroll
    for (int mt = 0; mt < 2; ++mt) {
        const float* qp = base + (size_t)(m0 + mt * 16 + g) * 384 + h * 16;
        float2 a0 = *(const float2*)(qp + 2 * tig);
        float2 a1 = *(const float2*)(qp + 8 * 384 + 2 * tig);
        float2 a2 = *(const float2*)(qp + 2 * tig + 8);
        float2 a3 = *(const float2*)(qp + 8 * 384 + 2 * tig + 8);
        qa[mt][0] = packbf(a0.x * QSC, a0.y * QSC);
        qa[mt][1] = packbf(a1.x * QSC, a1.y * QSC);
        qa[mt][2] = packbf(a2.x * QSC, a2.y * QSC);
        qa[mt][3] = packbf(a3.x * QSC, a3.y * QSC);
    }
    __syncthreads();

    float o[2][2][4];
    float lrow[2][2];
#pragma unroll
    for (int mt = 0; mt < 2; ++mt) {
        lrow[mt][0] = 0.f; lrow[mt][1] = 0.f;
#pragma unroll
        for (int nt = 0; nt < 2; ++nt)
#pragma unroll
            for (int r = 0; r < 4; ++r) o[mt][nt][r] = 0.f;
    }

    for (int j = 0; j < 16; ++j) {
        const int n0 = j * 32;
        uint32_t ps[2][2][4];

#pragma unroll
        for (int nt = 0; nt < 4; ++nt) {
            uint32_t bk[2];
            {
                const uint32_t* kp = Ksp + (n0 + nt * 8 + g) * KP_ST + tig;
                bk[0] = kp[0];
                bk[1] = kp[4];
            }
#pragma unroll
            for (int mt = 0; mt < 2; ++mt) {
                float c[4] = {0.f, 0.f, 0.f, 0.f};
                mma_bf16(c, qa[mt], bk);
                float p0 = fex2(c[0]);
                float p1 = fex2(c[1]);
                float p2 = fex2(c[2]);
                float p3 = fex2(c[3]);
                lrow[mt][0] += p0 + p1;
                lrow[mt][1] += p2 + p3;
                ps[mt][nt >> 1][(nt & 1) * 2 + 0] = packbf(p0, p1);
                ps[mt][nt >> 1][(nt & 1) * 2 + 1] = packbf(p2, p3);
            }
        }

#pragma unroll
        for (int c = 0; c < 2; ++c) {
            const int prb = (n0 >> 1) + c * 8;
#pragma unroll
            for (int nt = 0; nt < 2; ++nt) {
                uint32_t bv[2];
                const uint32_t* vp = Vsp + (prb + tig) * VP_ST + nt * 8 + g;
                bv[0] = vp[0];
                bv[1] = vp[4 * VP_ST];
#pragma unroll
                for (int mt = 0; mt < 2; ++mt)
                    mma_bf16(o[mt][nt], ps[mt][c], bv);
            }
        }
    }

#pragma unroll
    for (int mt = 0; mt < 2; ++mt) {
        float l0 = lrow[mt][0], l1 = lrow[mt][1];
        l0 += __shfl_xor_sync(0xffffffffu, l0, 1);
        l0 += __shfl_xor_sync(0xffffffffu, l0, 2);
        l1 += __shfl_xor_sync(0xffffffffu, l1, 1);
        l1 += __shfl_xor_sync(0xffffffffu, l1, 2);
        float i0 = 1.f / l0, i1 = 1.f / l1;
        int grow = gi * SEQ + m0 + mt * 16 + g;
#pragma unroll
        for (int nt = 0; nt < 2; ++nt) {
            int col = h * 16 + nt * 8 + 2 * tig;
            *(float2*)(ao + (size_t)grow * DD + col) =
                make_float2(o[mt][nt][0] * i0, o[mt][nt][1] * i0);
            *(float2*)(ao + (size_t)(grow + 8) * DD + col) =
                make_float2(o[mt][nt][2] * i1, o[mt][nt][3] * i1);
        }
    }
}

// =====================================================================
// BatchNorm apply (final)
// =====================================================================
__global__ void __launch_bounds__(256)
bn_apply_one(const float* __restrict__ X, const float* __restrict__ stats,
             const float* __restrict__ gamma, const float* __restrict__ beta,
             float* __restrict__ out)
{
    int col = threadIdx.x & 127;
    int half = threadIdx.x >> 7;
    float sc, sh;
    bn_coef(stats, gamma, beta, col, sc, sh);
    int row0 = blockIdx.x * 128 + half * 64;
    size_t off = (size_t)row0 * DD + col;
#pragma unroll 4
    for (int r = 0; r < 64; ++r)
        out[off + r * DD] = X[off + r * DD] * sc + sh;
}

// =====================================================================
// Host launcher — two-stream fork/join captured as a branching graph.
// =====================================================================
extern "C" void kernel_launch(void* const* d_in, const int* in_sizes, int n_in,
                              void* d_out, int out_size)
{
    const float* x          = (const float*)d_in[0];
    const int*   edge_index = (const int*)  d_in[1];
    const float* edge_attr  = (const float*)d_in[2];
    const float* gin_w1     = (const float*)d_in[3];
    const float* gin_b1     = (const float*)d_in[4];
    const float* gin_w2     = (const float*)d_in[5];
    const float* gin_b2     = (const float*)d_in[6];
    const float* bn1l_g     = (const float*)d_in[7];
    const float* bn1l_b     = (const float*)d_in[8];
    const float* in_proj_w  = (const float*)d_in[9];
    const float* in_proj_b  = (const float*)d_in[10];
    const float* out_proj_w = (const float*)d_in[11];
    const float* out_proj_b = (const float*)d_in[12];
    const float* bn1a_g     = (const float*)d_in[13];
    const float* bn1a_b     = (const float*)d_in[14];
    const float* ff_w1      = (const float*)d_in[15];
    const float* ff_b1      = (const float*)d_in[16];
    const float* ff_w2      = (const float*)d_in[17];
    const float* ff_b2      = (const float*)d_in[18];
    const float* bn2_g      = (const float*)d_in[19];
    const float* bn2_b      = (const float*)d_in[20];
    float* out = (float*)d_out;

    static cudaStream_t sB = nullptr;
    static cudaEvent_t evFork = nullptr, evJoin = nullptr;
    if (sB == nullptr) {
        cudaStreamCreateWithFlags(&sB, cudaStreamNonBlocking);
        cudaEventCreateWithFlags(&evFork, cudaEventDisableTiming);
        cudaEventCreateWithFlags(&evJoin, cudaEventDisableTiming);
        cudaFuncSetAttribute(attn_mma, cudaFuncAttributeMaxDynamicSharedMemorySize, ATTN_SMEM);
        cudaFuncSetAttribute(gemm_ar<false, false>, cudaFuncAttributeMaxDynamicSharedMemorySize, GEMM_AR_SMEM);
        cudaFuncSetAttribute(gemm_ar<true,  true >, cudaFuncAttributeMaxDynamicSharedMemorySize, GEMM_AR_SMEM);
        cudaFuncSetAttribute(mlp_fused<1, true, false>, cudaFuncAttributeMaxDynamicSharedMemorySize, MLP_SMEM);
        cudaFuncSetAttribute(mlp_fused<2, true, true >, cudaFuncAttributeMaxDynamicSharedMemorySize, MLP_SMEM);
    }

    float *z, *hl, *qkvb, *ao, *ha, *h2, *stats;
    int *deg, *off, *pos, *eid;
    cudaGetSymbolAddress((void**)&z,    g_z);
    cudaGetSymbolAddress((void**)&hl,   g_hl);
    cudaGetSymbolAddress((void**)&qkvb, g_qkv);
    cudaGetSymbolAddress((void**)&ao,   g_ao);
    cudaGetSymbolAddress((void**)&ha,   g_ha);
    cudaGetSymbolAddress((void**)&h2,   g_h2);
    cudaGetSymbolAddress((void**)&stats, g_stats);
    cudaGetSymbolAddress((void**)&deg,  g_deg);
    cudaGetSymbolAddress((void**)&off,  g_off);
    cudaGetSymbolAddress((void**)&pos,  g_pos);
    cudaGetSymbolAddress((void**)&eid,  g_eid);

    const int* src = edge_index;
    const int* dst = edge_index + EE;
    const dim3 blk(256);
    const int GB = NN / 128;

    float* stats_hl = stats;
    float* stats_ha = stats + 256;
    float* stats_h2 = stats + 512;

    // ---- common prologue on null stream ----
    zero_misc<<<64, blk>>>(deg, stats);                                            // 0

    // ---- fork: stream B = attention branch ----
    cudaEventRecord(evFork, 0);
    cudaStreamWaitEvent(sB, evFork, 0);

    gemm_ar<false, false><<<dim3(GB, 3), blk, GEMM_AR_SMEM, sB>>>(
        x, in_proj_w, in_proj_b, nullptr, qkvb, 384, nullptr);                     // 1 (B)
    count_kernel<<<EE / 256, blk>>>(dst, deg);                                     // 2 (A)
    attn_mma<<<NGR * NH * 2, blk, ATTN_SMEM, sB>>>(qkvb, ao);                      // 3 (B) <- profiled
    scan_kernel<<<1, 1024>>>(deg, off, pos);                                       // 4 (A)
    scatter_kernel<<<EE / 256, blk>>>(dst, pos, eid);                              // 5 (A)
    gemm_ar<true, true><<<dim3(GB, 1), blk, GEMM_AR_SMEM, sB>>>(
        ao, out_proj_w, out_proj_b, x, ha, 128, stats_ha);                         // 6 (B)
    aggr_kernel<<<NN / 8, blk>>>(x, src, edge_attr, off, eid, z);                  // 7 (A)
    mlp_fused<1, true, false><<<GB, blk, MLP_SMEM>>>(
        z, gin_w1, gin_b1, gin_w2, gin_b2, x, hl, stats_hl,
        nullptr, nullptr, nullptr, nullptr, nullptr, nullptr);                     // 8 (A)

    // ---- join ----
    cudaEventRecord(evJoin, sB);
    cudaStreamWaitEvent(0, evJoin, 0);

    // FFN with fused bn_dual input: A' = bn1a(ha) + bn1l(hl)
    mlp_fused<2, true, true><<<GB, blk, MLP_SMEM>>>(
        ha, ff_w1, ff_b1, ff_w2, ff_b2, hl, h2, stats_h2,
        stats_ha, bn1a_g, bn1a_b, stats_hl, bn1l_g, bn1l_b);                       // 9
    bn_apply_one<<<128, blk>>>(h2, stats_h2, bn2_g, bn2_b, out);                   // 10
}

// round 15
// speedup vs baseline: 1.1158x; 1.0197x over previous
#include <cuda_runtime.h>
#include <cuda_bf16.h>
#include <math.h>
#include <stdint.h>

// Problem constants
constexpr int NN  = 16384;   // nodes
constexpr int DD  = 128;     // dim
constexpr int EE  = 262144;  // edges
constexpr int SEQ = 512;     // nodes per graph
constexpr int NGR = 32;      // graphs
constexpr int NH  = 8;       // heads (dh = 16)

// ---------------- scratch ----------------
__device__ float g_z   [NN * DD];
__device__ float g_hl  [NN * DD];
__device__ float g_qkv [NN * 3 * DD];
__device__ float g_ao  [NN * DD];
__device__ float g_ha  [NN * DD];
__device__ float g_h2  [NN * DD];
__device__ float g_stats[768];
__device__ int   g_deg [NN];
__device__ int   g_off [NN + 1];
__device__ int   g_pos [NN];
__device__ int   g_eid [EE];

// =====================================================================
__global__ void zero_misc(int* deg, float* stats)
{
    int i = blockIdx.x * 256 + threadIdx.x;
    deg[i] = 0;
    if (i < 768) stats[i] = 0.f;
}

// =====================================================================
// CSR build by dst:  count -> scan -> scatter
// =====================================================================
__global__ void count_kernel(const int* __restrict__ dst, int* __restrict__ deg)
{
    int e = blockIdx.x * 256 + threadIdx.x;
    atomicAdd(&deg[dst[e]], 1);
}

__global__ void __launch_bounds__(1024)
scan_kernel(const int* __restrict__ deg, int* __restrict__ off, int* __restrict__ pos)
{
    __shared__ int buf[2][1024];
    int t = threadIdx.x;
    int base = t * 16;
    int loc[16];
    int sum = 0;
#pragma unroll
    for (int i = 0; i < 16; ++i) { loc[i] = sum; sum += deg[base + i]; }
    buf[0][t] = sum;
    __syncthreads();
    int sel = 0;
    for (int d = 1; d < 1024; d <<= 1) {
        int v = buf[sel][t] + (t >= d ? buf[sel][t - d] : 0);
        buf[sel ^ 1][t] = v;
        sel ^= 1;
        __syncthreads();
    }
    int excl = buf[sel][t] - sum;
#pragma unroll
    for (int i = 0; i < 16; ++i) {
        int o = excl + loc[i];
        off[base + i] = o;
        pos[base + i] = o;
    }
    if (t == 1023) off[NN] = excl + sum;
}

__global__ void scatter_kernel(const int* __restrict__ dst, int* __restrict__ pos,
                               int* __restrict__ eid)
{
    int e = blockIdx.x * 256 + threadIdx.x;
    int p = atomicAdd(&pos[dst[e]], 1);
    eid[p] = e;
}

// =====================================================================
// Gather aggregation: z = x + sum_{e -> node} relu(x[src[e]] + ea[e])
// =====================================================================
__global__ void __launch_bounds__(256)
aggr_kernel(const float* __restrict__ x, const int* __restrict__ src,
            const float* __restrict__ ea, const int* __restrict__ off,
            const int* __restrict__ eid, float* __restrict__ z)
{
    int node = blockIdx.x * 8 + (threadIdx.x >> 5);
    int lane = threadIdx.x & 31;
    int beg = off[node], end = off[node + 1];
    const float4* x4  = (const float4*)x;
    const float4* ea4 = (const float4*)ea;
    float4 acc = make_float4(0.f, 0.f, 0.f, 0.f);
#pragma unroll 2
    for (int i = beg; i < end; ++i) {
        int e = __ldg(eid + i);
        int s = __ldg(src + e);
        float4 a = x4[(size_t)s * 32 + lane];
        float4 b = ea4[(size_t)e * 32 + lane];
        acc.x += fmaxf(a.x + b.x, 0.f);
        acc.y += fmaxf(a.y + b.y, 0.f);
        acc.z += fmaxf(a.z + b.z, 0.f);
        acc.w += fmaxf(a.w + b.w, 0.f);
    }
    float4 xv = x4[(size_t)node * 32 + lane];
    ((float4*)z)[(size_t)node * 32 + lane] =
        make_float4(xv.x + acc.x, xv.y + acc.y, xv.z + acc.z, xv.w + acc.w);
}

// =====================================================================
// mma helpers
// =====================================================================
__device__ __forceinline__ uint32_t to_tf32(float f)
{
    uint32_t u;
    asm("cvt.rna.tf32.f32 %0, %1;" : "=r"(u) : "f"(f));
    return u;
}

__device__ __forceinline__ void mma_tf32(float c[4], const uint32_t a[4], const uint32_t b[2])
{
    asm volatile(
        "mma.sync.aligned.m16n8k8.row.col.f32.tf32.tf32.f32 "
        "{%0,%1,%2,%3}, {%4,%5,%6,%7}, {%8,%9}, {%0,%1,%2,%3};\n"
        : "+f"(c[0]), "+f"(c[1]), "+f"(c[2]), "+f"(c[3])
        : "r"(a[0]), "r"(a[1]), "r"(a[2]), "r"(a[3]), "r"(b[0]), "r"(b[1]));
}

__device__ __forceinline__ void mma_bf16(float c[4], const uint32_t a[4], const uint32_t b[2])
{
    asm volatile(
        "mma.sync.aligned.m16n8k16.row.col.f32.bf16.bf16.f32 "
        "{%0,%1,%2,%3}, {%4,%5,%6,%7}, {%8,%9}, {%0,%1,%2,%3};\n"
        : "+f"(c[0]), "+f"(c[1]), "+f"(c[2]), "+f"(c[3])
        : "r"(a[0]), "r"(a[1]), "r"(a[2]), "r"(a[3]), "r"(b[0]), "r"(b[1]));
}

__device__ __forceinline__ uint32_t packbf(float lo, float hi)
{
    uint32_t r;
    asm("cvt.rn.bf16x2.f32 %0, %1, %2;" : "=r"(r) : "f"(hi), "f"(lo));
    return r;
}

__device__ __forceinline__ float fex2(float x)
{
    float y;
    asm("ex2.approx.f32 %0, %1;" : "=f"(y) : "f"(x));
    return y;
}

constexpr int AST  = 132;   // A/T smem stride (u32, tf32)
constexpr int BST  = 20;    // [n][k] B-chunk stride (gemm_ar tf32)
constexpr int BSTK = 132;   // [k][n] B-chunk stride (mlp_fused)
constexpr int ABH  = 68;    // A stride for bf16-pair layout (4g+tig conflict-free)
constexpr int BBH  = 12;    // B stride for bf16-pair layout (12g+tig conflict-free)

// one 16-k-slab: A-src (stride AST), B-chunk [n][k] (stride BST)
__device__ __forceinline__ void mma_slab16(const uint32_t* S, const uint32_t* Bb,
                                           float acc[4][4][4],
                                           int wm, int wn, int g, int tig, int kt)
{
#pragma unroll
    for (int k8s = 0; k8s < 2; ++k8s) {
        const int kk = kt * 16 + k8s * 8;
        uint32_t af[4][4];
#pragma unroll
        for (int mf = 0; mf < 4; ++mf) {
            const uint32_t* pa = S + (wm * 64 + mf * 16 + g) * AST + kk + tig;
            af[mf][0] = pa[0];
            af[mf][1] = pa[8 * AST];
            af[mf][2] = pa[4];
            af[mf][3] = pa[8 * AST + 4];
        }
        uint32_t bf[4][2];
#pragma unroll
        for (int nf = 0; nf < 4; ++nf) {
            const uint32_t* pb = Bb + (wn * 32 + nf * 8 + g) * BST + k8s * 8 + tig;
            bf[nf][0] = pb[0];
            bf[nf][1] = pb[4];
        }
#pragma unroll
        for (int mf = 0; mf < 4; ++mf)
#pragma unroll
            for (int nf = 0; nf < 4; ++nf)
                mma_tf32(acc[mf][nf], af[mf], bf[nf]);
    }
}

// one 16-k-slab: A-src (stride AST), B-chunk [k][n] (stride BSTK; 16 rows)
__device__ __forceinline__ void mma_slab16_kn(const uint32_t* S, const uint32_t* Bkn,
                                              float acc[4][4][4],
                                              int wm, int wn, int g, int tig, int kt)
{
#pragma unroll
    for (int k8s = 0; k8s < 2; ++k8s) {
        const int kk = kt * 16 + k8s * 8;
        uint32_t af[4][4];
#pragma unroll
        for (int mf = 0; mf < 4; ++mf) {
            const uint32_t* pa = S + (wm * 64 + mf * 16 + g) * AST + kk + tig;
            af[mf][0] = pa[0];
            af[mf][1] = pa[8 * AST];
            af[mf][2] = pa[4];
            af[mf][3] = pa[8 * AST + 4];
        }
        uint32_t bf[4][2];
        const uint32_t* pb0 = Bkn + (k8s * 8 + tig) * BSTK;
        const uint32_t* pb1 = pb0 + 4 * BSTK;
#pragma unroll
        for (int nf = 0; nf < 4; ++nf) {
            int n = wn * 32 + nf * 8 + g;
            bf[nf][0] = pb0[n];
            bf[nf][1] = pb1[n];
        }
#pragma unroll
        for (int mf = 0; mf < 4; ++mf)
#pragma unroll
            for (int nf = 0; nf < 4; ++nf)
                mma_tf32(acc[mf][nf], af[mf], bf[nf]);
    }
}

// epilogue shared by all GEMM kernels (MF=4)
template<bool RELU, bool RESID, bool STATS, bool BNRES>
__device__ __forceinline__ void gemm_epilogue(
    float acc[4][4][4], const float* bias, const float* resid,
    float* C, int ldc, int m0, int n0,
    int wm, int wn, int g, int tig, int tid,
    float* stats, float* sst,
    const float* haP, const float* hlP, const float* coef)
{
    float cs[8], cq[8];
    if (STATS) {
#pragma unroll
        for (int j = 0; j < 8; ++j) { cs[j] = 0.f; cq[j] = 0.f; }
    }
#pragma unroll
    for (int mf = 0; mf < 4; ++mf) {
#pragma unroll
        for (int nf = 0; nf < 4; ++nf) {
            int row = m0 + wm * 64 + mf * 16 + g;
            int col = n0 + wn * 32 + nf * 8 + 2 * tig;
            float b0 = bias[col], b1 = bias[col + 1];
            float o00 = acc[mf][nf][0] + b0, o01 = acc[mf][nf][1] + b1;
            float o10 = acc[mf][nf][2] + b0, o11 = acc[mf][nf][3] + b1;
            if (RELU) {
                o00 = fmaxf(o00, 0.f); o01 = fmaxf(o01, 0.f);
                o10 = fmaxf(o10, 0.f); o11 = fmaxf(o11, 0.f);
            }
            if (RESID) {
                float2 r0, r1;
                if (BNRES) {
                    float sA0 = coef[col],       hA0 = coef[128 + col];
                    float sA1 = coef[col + 1],   hA1 = coef[128 + col + 1];
                    float sL0 = coef[256 + col], hL0 = coef[384 + col];
                    float sL1 = coef[256 + col + 1], hL1 = coef[384 + col + 1];
                    float2 a0 = *(const float2*)(haP + (size_t)row * ldc + col);
                    float2 a1 = *(const float2*)(haP + (size_t)(row + 8) * ldc + col);
                    float2 l0 = *(const float2*)(hlP + (size_t)row * ldc + col);
                    float2 l1 = *(const float2*)(hlP + (size_t)(row + 8) * ldc + col);
                    r0.x = a0.x * sA0 + hA0 + l0.x * sL0 + hL0;
                    r0.y = a0.y * sA1 + hA1 + l0.y * sL1 + hL1;
                    r1.x = a1.x * sA0 + hA0 + l1.x * sL0 + hL0;
                    r1.y = a1.y * sA1 + hA1 + l1.y * sL1 + hL1;
                } else {
                    r0 = *(const float2*)(resid + (size_t)row * ldc + col);
                    r1 = *(const float2*)(resid + (size_t)(row + 8) * ldc + col);
                }
                o00 += r0.x; o01 += r0.y;
                o10 += r1.x; o11 += r1.y;
            }
            if (STATS) {
                cs[nf*2]   += o00 + o10;
                cs[nf*2+1] += o01 + o11;
                cq[nf*2]   += o00*o00 + o10*o10;
                cq[nf*2+1] += o01*o01 + o11*o11;
            }
            *(float2*)(C + (size_t)row * ldc + col)       = make_float2(o00, o01);
            *(float2*)(C + (size_t)(row + 8) * ldc + col) = make_float2(o10, o11);
        }
    }
    if (STATS) {
        __syncthreads();
        sst[tid] = 0.f;
        __syncthreads();
#pragma unroll
        for (int j = 0; j < 8; ++j) {
            int col = wn * 32 + (j >> 1) * 8 + 2 * tig + (j & 1);
            atomicAdd(&sst[col],       cs[j]);
            atomicAdd(&sst[128 + col], cq[j]);
        }
        __syncthreads();
        atomicAdd(&stats[tid], sst[tid]);
    }
}

// BN coefficient helper
__device__ __forceinline__ void bn_coef(const float* stats, const float* gamma,
                                        const float* beta, int col,
                                        float& sc, float& sh)
{
    float mean = stats[col] * (1.f / (float)NN);
    float var  = stats[128 + col] * (1.f / (float)NN) - mean * mean;
    sc = gamma[col] * rsqrtf(var + 1e-5f);
    sh = beta[col] - mean * sc;
}

// =====================================================================
// BF16 A-resident GEMM (K=128) — used for QKV only (feeds bf16 attention).
// C = A @ B^T + bias. A packed bf16x2 pairs [128][ABH]; B chunks [n][BBH].
// Double-buffered, one sync per k-chunk. 128 bf16 mma per block.
// =====================================================================
constexpr int GEMM_BF_SMEM = (128 * ABH + 2 * 128 * BBH) * 4;   // ~47KB

__global__ void __launch_bounds__(256, 2)
gemm_qkv_bf16(const float* __restrict__ A,
              const float* __restrict__ B,
              const float* __restrict__ bias,
              float* __restrict__ C, int ldc)
{
    extern __shared__ uint32_t sm[];
    uint32_t* Abuf = sm;                 // [128][ABH] bf16x2 pairs
    uint32_t* Bb0  = sm + 128 * ABH;     // [128][BBH] stage 0
    uint32_t* Bb1  = Bb0 + 128 * BBH;    // stage 1

    const int tid = threadIdx.x;
    const int lane = tid & 31, warp = tid >> 5;
    const int wm = warp >> 2, wn = warp & 3;
    const int g = lane >> 2, tig = lane & 3;
    const int m0 = blockIdx.x * 128;
    const int n0 = blockIdx.y * 128;
    const int i0 = tid, i1 = tid + 256;
    const float* Bp0 = B + (size_t)(n0 + (i0 >> 2)) * 128 + (i0 & 3) * 4;
    const float* Bp1 = B + (size_t)(n0 + (i1 >> 2)) * 128 + (i1 & 3) * 4;
    const int o0 = (i0 >> 2) * BBH + (i0 & 3) * 2;   // pair offsets
    const int o1 = (i1 >> 2) * BBH + (i1 & 3) * 2;

    // stage A (pack pairs along k)
#pragma unroll
    for (int it = 0; it < 16; ++it) {
        int idx = tid + it * 256;
        int r = idx >> 5, c4 = (idx & 31) * 4;
        float4 v = *(const float4*)(A + (size_t)(m0 + r) * 128 + c4);
        uint32_t* d = Abuf + r * ABH + (c4 >> 1);
        d[0] = packbf(v.x, v.y);
        d[1] = packbf(v.z, v.w);
    }

    float acc[4][4][4];
#pragma unroll
    for (int i = 0; i < 4; ++i)
#pragma unroll
        for (int j = 0; j < 4; ++j)
#pragma unroll
            for (int r = 0; r < 4; ++r) acc[i][j][r] = 0.f;

    // chunk 0 -> stage 0, prefetch chunk 1
    float4 pre0 = *(const float4*)(Bp0);
    float4 pre1 = *(const float4*)(Bp1);
    {
        uint32_t* d0 = Bb0 + o0;
        d0[0] = packbf(pre0.x, pre0.y); d0[1] = packbf(pre0.z, pre0.w);
        uint32_t* d1 = Bb0 + o1;
        d1[0] = packbf(pre1.x, pre1.y); d1[1] = packbf(pre1.z, pre1.w);
    }
    pre0 = *(const float4*)(Bp0 + 16);
    pre1 = *(const float4*)(Bp1 + 16);
    __syncthreads();

    for (int kt = 0; kt < 8; ++kt) {
        if (kt < 7) {
            uint32_t* stg = (kt & 1) ? Bb0 : Bb1;
            uint32_t* d0 = stg + o0;
            d0[0] = packbf(pre0.x, pre0.y); d0[1] = packbf(pre0.z, pre0.w);
            uint32_t* d1 = stg + o1;
            d1[0] = packbf(pre1.x, pre1.y); d1[1] = packbf(pre1.z, pre1.w);
            if (kt < 6) {
                pre0 = *(const float4*)(Bp0 + (kt + 2) * 16);
                pre1 = *(const float4*)(Bp1 + (kt + 2) * 16);
            }
        }
        // mma: one k16 slab (bf16)
        {
            const uint32_t* Bb = (kt & 1) ? Bb1 : Bb0;
            uint32_t af[4][4];
#pragma unroll
            for (int mf = 0; mf < 4; ++mf) {
                const uint32_t* pa = Abuf + (wm * 64 + mf * 16 + g) * ABH + kt * 8 + tig;
                af[mf][0] = pa[0];
                af[mf][1] = pa[8 * ABH];
                af[mf][2] = pa[4];
                af[mf][3] = pa[8 * ABH + 4];
            }
            uint32_t bf[4][2];
#pragma unroll
            for (int nf = 0; nf < 4; ++nf) {
                const uint32_t* pb = Bb + (wn * 32 + nf * 8 + g) * BBH + tig;
                bf[nf][0] = pb[0];
                bf[nf][1] = pb[4];
            }
#pragma unroll
            for (int mf = 0; mf < 4; ++mf)
#pragma unroll
                for (int nf = 0; nf < 4; ++nf)
                    mma_bf16(acc[mf][nf], af[mf], bf[nf]);
        }
        if (kt < 7) __syncthreads();
    }

    // epilogue: bias + store
#pragma unroll
    for (int mf = 0; mf < 4; ++mf) {
#pragma unroll
        for (int nf = 0; nf < 4; ++nf) {
            int row = m0 + wm * 64 + mf * 16 + g;
            int col = n0 + wn * 32 + nf * 8 + 2 * tig;
            float b0 = bias[col], b1 = bias[col + 1];
            *(float2*)(C + (size_t)row * ldc + col) =
                make_float2(acc[mf][nf][0] + b0, acc[mf][nf][1] + b1);
            *(float2*)(C + (size_t)(row + 8) * ldc + col) =
                make_float2(acc[mf][nf][2] + b0, acc[mf][nf][3] + b1);
        }
    }
}

// =====================================================================
// A-resident TF32 GEMM (K=128): used for out_proj (precision-sensitive).
// =====================================================================
constexpr int GEMM_AR_SMEM = (128 * AST + 2 * 128 * BST) * 4;

template<bool RESID, bool STATS>
__global__ void __launch_bounds__(256, 2)
gemm_ar(const float* __restrict__ A,
        const float* __restrict__ B,
        const float* __restrict__ bias,
        const float* __restrict__ resid,
        float* __restrict__ C, int ldc,
        float* __restrict__ stats)
{
    extern __shared__ uint32_t sm[];
    uint32_t* Abuf = sm;
    uint32_t* Bb0  = sm + 128 * AST;
    uint32_t* Bb1  = Bb0 + 128 * BST;

    const int tid = threadIdx.x;
    const int lane = tid & 31, warp = tid >> 5;
    const int wm = warp >> 2, wn = warp & 3;
    const int g = lane >> 2, tig = lane & 3;
    const int m0 = blockIdx.x * 128;
    const int n0 = blockIdx.y * 128;
    const int i0 = tid, i1 = tid + 256;
    const float* Bp0 = B + (size_t)(n0 + (i0 >> 2)) * 128 + (i0 & 3) * 4;
    const float* Bp1 = B + (size_t)(n0 + (i1 >> 2)) * 128 + (i1 & 3) * 4;
    const int o0 = (i0 >> 2) * BST + (i0 & 3) * 4;
    const int o1 = (i1 >> 2) * BST + (i1 & 3) * 4;

#pragma unroll
    for (int it = 0; it < 16; ++it) {
        int idx = tid + it * 256;
        int r = idx >> 5, c4 = (idx & 31) * 4;
        float4 v = *(const float4*)(A + (size_t)(m0 + r) * 128 + c4);
        uint32_t* d = Abuf + r * AST + c4;
        d[0] = to_tf32(v.x); d[1] = to_tf32(v.y);
        d[2] = to_tf32(v.z); d[3] = to_tf32(v.w);
    }

    float acc[4][4][4];
#pragma unroll
    for (int i = 0; i < 4; ++i)
#pragma unroll
        for (int j = 0; j < 4; ++j)
#pragma unroll
            for (int r = 0; r < 4; ++r) acc[i][j][r] = 0.f;

    float4 pre0 = *(const float4*)(Bp0);
    float4 pre1 = *(const float4*)(Bp1);
    {
        uint32_t* d0 = Bb0 + o0;
        d0[0] = to_tf32(pre0.x); d0[1] = to_tf32(pre0.y);
        d0[2] = to_tf32(pre0.z); d0[3] = to_tf32(pre0.w);
        uint32_t* d1 = Bb0 + o1;
        d1[0] = to_tf32(pre1.x); d1[1] = to_tf32(pre1.y);
        d1[2] = to_tf32(pre1.z); d1[3] = to_tf32(pre1.w);
    }
    pre0 = *(const float4*)(Bp0 + 16);
    pre1 = *(const float4*)(Bp1 + 16);
    __syncthreads();

    for (int kt = 0; kt < 8; ++kt) {
        if (kt < 7) {
            uint32_t* stg = (kt & 1) ? Bb0 : Bb1;
            uint32_t* d0 = stg + o0;
            d0[0] = to_tf32(pre0.x); d0[1] = to_tf32(pre0.y);
            d0[2] = to_tf32(pre0.z); d0[3] = to_tf32(pre0.w);
            uint32_t* d1 = stg + o1;
            d1[0] = to_tf32(pre1.x); d1[1] = to_tf32(pre1.y);
            d1[2] = to_tf32(pre1.z); d1[3] = to_tf32(pre1.w);
            if (kt < 6) {
                pre0 = *(const float4*)(Bp0 + (kt + 2) * 16);
                pre1 = *(const float4*)(Bp1 + (kt + 2) * 16);
            }
        }
        mma_slab16(Abuf, (kt & 1) ? Bb1 : Bb0, acc, wm, wn, g, tig, kt);
        if (kt < 7) __syncthreads();
    }

    gemm_epilogue<false, RESID, STATS, false>(acc, bias, resid, C, ldc, m0, n0,
                                              wm, wn, g, tig, tid, stats, (float*)Bb0,
                                              nullptr, nullptr, nullptr);
}

// =====================================================================
// Fused MLP: C = relu(A' @ W1 + b1) @ W2 + b2 + resid' (+stats)
// BNIN: A' = bnA(A=ha) + bnL(resid=hl) inline; residual recomputed in epilogue.
// =====================================================================
constexpr int MLP_SMEM = (2 * 128 * AST + 2 * 16 * BSTK) * 4;   // ~152KB

template<int NC, bool STATS, bool BNIN>
__global__ void __launch_bounds__(256, 1)
mlp_fused(const float* __restrict__ A,
          const float* __restrict__ W1, const float* __restrict__ b1,
          const float* __restrict__ W2, const float* __restrict__ b2,
          const float* __restrict__ resid,
          float* __restrict__ C,
          float* __restrict__ stats,
          const float* __restrict__ stA, const float* __restrict__ gA,
          const float* __restrict__ bA,
          const float* __restrict__ stL, const float* __restrict__ gL,
          const float* __restrict__ bL)
{
    extern __shared__ uint32_t sm[];
    uint32_t* Abuf = sm;                   // [128][AST]
    uint32_t* Tbuf = sm + 128 * AST;       // [128][AST]
    uint32_t* Bb0  = sm + 2 * 128 * AST;   // [16][BSTK] stage 0
    uint32_t* Bb1  = Bb0 + 16 * BSTK;      // [16][BSTK] stage 1
    __shared__ float coef[512];

    const int tid = threadIdx.x;
    const int lane = tid & 31, warp = tid >> 5;
    const int wm = warp >> 2, wn = warp & 3;
    const int g = lane >> 2, tig = lane & 3;
    const int m0 = blockIdx.x * 128;
    const int ldw1 = NC * 128;

    const int i0 = tid, i1 = tid + 256;
    const int k0 = i0 >> 5, c40 = (i0 & 31) * 4;
    const int k1 = i1 >> 5, c41 = (i1 & 31) * 4;
    const int o0 = k0 * BSTK + c40;
    const int o1 = k1 * BSTK + c41;

    if (BNIN) {
        if (tid < 128) {
            float sc, sh;
            bn_coef(stA, gA, bA, tid, sc, sh);
            coef[tid] = sc; coef[128 + tid] = sh;
            bn_coef(stL, gL, bL, tid, sc, sh);
            coef[256 + tid] = sc; coef[384 + tid] = sh;
        }
        __syncthreads();
    }

#pragma unroll
    for (int it = 0; it < 16; ++it) {
        int idx = tid + it * 256;
        int r = idx >> 5, c4 = (idx & 31) * 4;
        float4 v = *(const float4*)(A + (size_t)(m0 + r) * 128 + c4);
        if (BNIN) {
            float4 w = *(const float4*)(resid + (size_t)(m0 + r) * 128 + c4);
            v.x = v.x * coef[c4]     + coef[128 + c4]     + w.x * coef[256 + c4]     + coef[384 + c4];
            v.y = v.y * coef[c4 + 1] + coef[128 + c4 + 1] + w.y * coef[256 + c4 + 1] + coef[384 + c4 + 1];
            v.z = v.z * coef[c4 + 2] + coef[128 + c4 + 2] + w.z * coef[256 + c4 + 2] + coef[384 + c4 + 2];
            v.w = v.w * coef[c4 + 3] + coef[128 + c4 + 3] + w.w * coef[256 + c4 + 3] + coef[384 + c4 + 3];
        }
        uint32_t* d = Abuf + r * AST + c4;
        d[0] = to_tf32(v.x); d[1] = to_tf32(v.y);
        d[2] = to_tf32(v.z); d[3] = to_tf32(v.w);
    }

    float co[4][4][4];
#pragma unroll
    for (int i = 0; i < 4; ++i)
#pragma unroll
        for (int j = 0; j < 4; ++j)
#pragma unroll
            for (int r = 0; r < 4; ++r) co[i][j][r] = 0.f;

#pragma unroll
    for (int nc = 0; nc < NC; ++nc) {
        // ============ phase 1: c1 = A' @ W1[:, nc*128..] ============
        float c1[4][4][4];
#pragma unroll
        for (int i = 0; i < 4; ++i)
#pragma unroll
            for (int j = 0; j < 4; ++j)
#pragma unroll
                for (int r = 0; r < 4; ++r) c1[i][j][r] = 0.f;

        const float* Wp = W1 + nc * 128;
        float4 pre0 = *(const float4*)(Wp + (size_t)k0 * ldw1 + c40);
        float4 pre1 = *(const float4*)(Wp + (size_t)k1 * ldw1 + c41);
        if (nc) __syncthreads();
        {
            uint32_t* d0 = Bb0 + o0;
            d0[0] = to_tf32(pre0.x); d0[1] = to_tf32(pre0.y);
            d0[2] = to_tf32(pre0.z); d0[3] = to_tf32(pre0.w);
            uint32_t* d1 = Bb0 + o1;
            d1[0] = to_tf32(pre1.x); d1[1] = to_tf32(pre1.y);
            d1[2] = to_tf32(pre1.z); d1[3] = to_tf32(pre1.w);
        }
        pre0 = *(const float4*)(Wp + (size_t)(16 + k0) * ldw1 + c40);
        pre1 = *(const float4*)(Wp + (size_t)(16 + k1) * ldw1 + c41);
        __syncthreads();

        for (int kt = 0; kt < 8; ++kt) {
            if (kt < 7) {
                uint32_t* stg = (kt & 1) ? Bb0 : Bb1;
                uint32_t* d0 = stg + o0;
                d0[0] = to_tf32(pre0.x); d0[1] = to_tf32(pre0.y);
                d0[2] = to_tf32(pre0.z); d0[3] = to_tf32(pre0.w);
                uint32_t* d1 = stg + o1;
                d1[0] = to_tf32(pre1.x); d1[1] = to_tf32(pre1.y);
                d1[2] = to_tf32(pre1.z); d1[3] = to_tf32(pre1.w);
                if (kt < 6) {
                    pre0 = *(const float4*)(Wp + (size_t)((kt + 2) * 16 + k0) * ldw1 + c40);
                    pre1 = *(const float4*)(Wp + (size_t)((kt + 2) * 16 + k1) * ldw1 + c41);
                }
            }
            mma_slab16_kn(Abuf, (kt & 1) ? Bb1 : Bb0, c1, wm, wn, g, tig, kt);
            if (kt < 7) __syncthreads();
        }

        // write hidden tile: relu(c1 + b1chunk) -> Tbuf (tf32)
#pragma unroll
        for (int mf = 0; mf < 4; ++mf) {
#pragma unroll
            for (int nf = 0; nf < 4; ++nf) {
                int row = wm * 64 + mf * 16 + g;
                int col = wn * 32 + nf * 8 + 2 * tig;
                float bb0 = b1[nc * 128 + col], bb1 = b1[nc * 128 + col + 1];
                Tbuf[row * AST + col]           = to_tf32(fmaxf(c1[mf][nf][0] + bb0, 0.f));
                Tbuf[row * AST + col + 1]       = to_tf32(fmaxf(c1[mf][nf][1] + bb1, 0.f));
                Tbuf[(row + 8) * AST + col]     = to_tf32(fmaxf(c1[mf][nf][2] + bb0, 0.f));
                Tbuf[(row + 8) * AST + col + 1] = to_tf32(fmaxf(c1[mf][nf][3] + bb1, 0.f));
            }
        }

        // ============ phase 2: co += T @ W2[nc*128.., :] ============
        const float* W2p = W2 + (size_t)(nc * 128) * 128;
        pre0 = *(const float4*)(W2p + (size_t)k0 * 128 + c40);
        pre1 = *(const float4*)(W2p + (size_t)k1 * 128 + c41);
        __syncthreads();
        {
            uint32_t* d0 = Bb0 + o0;
            d0[0] = to_tf32(pre0.x); d0[1] = to_tf32(pre0.y);
            d0[2] = to_tf32(pre0.z); d0[3] = to_tf32(pre0.w);
            uint32_t* d1 = Bb0 + o1;
            d1[0] = to_tf32(pre1.x); d1[1] = to_tf32(pre1.y);
            d1[2] = to_tf32(pre1.z); d1[3] = to_tf32(pre1.w);
        }
        pre0 = *(const float4*)(W2p + (size_t)(16 + k0) * 128 + c40);
        pre1 = *(const float4*)(W2p + (size_t)(16 + k1) * 128 + c41);
        __syncthreads();

        for (int kt = 0; kt < 8; ++kt) {
            if (kt < 7) {
                uint32_t* stg = (kt & 1) ? Bb0 : Bb1;
                uint32_t* d0 = stg + o0;
                d0[0] = to_tf32(pre0.x); d0[1] = to_tf32(pre0.y);
                d0[2] = to_tf32(pre0.z); d0[3] = to_tf32(pre0.w);
                uint32_t* d1 = stg + o1;
                d1[0] = to_tf32(pre1.x); d1[1] = to_tf32(pre1.y);
                d1[2] = to_tf32(pre1.z); d1[3] = to_tf32(pre1.w);
                if (kt < 6) {
                    pre0 = *(const float4*)(W2p + (size_t)((kt + 2) * 16 + k0) * 128 + c40);
                    pre1 = *(const float4*)(W2p + (size_t)((kt + 2) * 16 + k1) * 128 + c41);
                }
            }
            mma_slab16_kn(Tbuf, (kt & 1) ? Bb1 : Bb0, co, wm, wn, g, tig, kt);
            if (kt < 7) __syncthreads();
        }
    }

    gemm_epilogue<false, true, STATS, BNIN>(co, b2, resid, C, 128, m0, 0,
                                            wm, wn, g, tig, tid, stats, (float*)Bb0,
                                            A, resid, coef);
}

// =====================================================================
// Flash-style BF16 attention v4: exp2-domain scores, occupancy 3.
// =====================================================================
constexpr int KP_ST = 12;
constexpr int VP_ST = 24;
constexpr int ATTN_SMEM = (512 * KP_ST + 256 * VP_ST) * 4;   // 48KB

__global__ void __launch_bounds__(256, 3)
attn_mma(const float* __restrict__ qkv, float* __restrict__ ao)
{
    extern __shared__ uint32_t sm[];
    uint32_t* Ksp = sm;
    uint32_t* Vsp = sm + 512 * KP_ST;

    const int tid  = threadIdx.x;
    const int lane = tid & 31;
    const int warp = tid >> 5;
    const int g    = lane >> 2;
    const int tig  = lane & 3;
    const int b    = blockIdx.x;
    const int gi = b >> 4, h = (b >> 1) & 7, half = b & 1;
    const float* base = qkv + (size_t)gi * SEQ * 384;
    const int m0 = half * 256 + warp * 32;
    const float QSC = 0.25f * 1.44269504f;

    for (int idx = tid; idx < 2048; idx += 256) {
        int r = idx >> 2, c4 = (idx & 3) * 4;
        float4 kv = *(const float4*)(base + (size_t)r * 384 + 128 + h * 16 + c4);
        Ksp[r * KP_ST + (c4 >> 1)]     = packbf(kv.x, kv.y);
        Ksp[r * KP_ST + (c4 >> 1) + 1] = packbf(kv.z, kv.w);
        if (idx < 1024) {
            int pr = r, dg = c4;
            float4 v0 = *(const float4*)(base + (size_t)(2 * pr)     * 384 + 256 + h * 16 + dg);
            float4 v1 = *(const float4*)(base + (size_t)(2 * pr + 1) * 384 + 256 + h * 16 + dg);
            uint32_t* vd = Vsp + pr * VP_ST + dg;
            vd[0] = packbf(v0.x, v1.x);
            vd[1] = packbf(v0.y, v1.y);
            vd[2] = packbf(v0.z, v1.z);
            vd[3] = packbf(v0.w, v1.w);
        }
    }

    uint32_t qa[2][4];
#pragma unroll
    for (int mt = 0; mt < 2; ++mt) {
        const float* qp = base + (size_t)(m0 + mt * 16 + g) * 384 + h * 16;
        float2 a0 = *(const float2*)(qp + 2 * tig);
        float2 a1 = *(const float2*)(qp + 8 * 384 + 2 * tig);
        float2 a2 = *(const float2*)(qp + 2 * tig + 8);
        float2 a3 = *(const float2*)(qp + 8 * 384 + 2 * tig + 8);
        qa[mt][0] = packbf(a0.x * QSC, a0.y * QSC);
        qa[mt][1] = packbf(a1.x * QSC, a1.y * QSC);
        qa[mt][2] = packbf(a2.x * QSC, a2.y * QSC);
        qa[mt][3] = packbf(a3.x * QSC, a3.y * QSC);
    }
    __syncthreads();

    float o[2][2][4];
    float lrow[2][2];
#pragma unroll
    for (int mt = 0; mt < 2; ++mt) {
        lrow[mt][0] = 0.f; lrow[mt][1] = 0.f;
#pragma unroll
        for (int nt = 0; nt < 2; ++nt)
#pragma unroll
            for (int r = 0; r < 4; ++r) o[mt][nt][r] = 0.f;
    }

    for (int j = 0; j < 16; ++j) {
        const int n0 = j * 32;
        uint32_t ps[2][2][4];

#pragma unroll
        for (int nt = 0; nt < 4; ++nt) {
            uint32_t bk[2];
            {
                const uint32_t* kp = Ksp + (n0 + nt * 8 + g) * KP_ST + tig;
                bk[0] = kp[0];
                bk[1] = kp[4];
            }
#pragma unroll
            for (int mt = 0; mt < 2; ++mt) {
                float c[4] = {0.f, 0.f, 0.f, 0.f};
                mma_bf16(c, qa[mt], bk);
                float p0 = fex2(c[0]);
                float p1 = fex2(c[1]);
                float p2 = fex2(c[2]);
                float p3 = fex2(c[3]);
                lrow[mt][0] += p0 + p1;
                lrow[mt][1] += p2 + p3;
                ps[mt][nt >> 1][(nt & 1) * 2 + 0] = packbf(p0, p1);
                ps[mt][nt >> 1][(nt & 1) * 2 + 1] = packbf(p2, p3);
            }
        }

#pragma unroll
        for (int c = 0; c < 2; ++c) {
            const int prb = (n0 >> 1) + c * 8;
#pragma unroll
            for (int nt = 0; nt < 2; ++nt) {
                uint32_t bv[2];
                const uint32_t* vp = Vsp + (prb + tig) * VP_ST + nt * 8 + g;
                bv[0] = vp[0];
                bv[1] = vp[4 * VP_ST];
#pragma unroll
                for (int mt = 0; mt < 2; ++mt)
                    mma_bf16(o[mt][nt], ps[mt][c], bv);
            }
        }
    }

#pragma unroll
    for (int mt = 0; mt < 2; ++mt) {
        float l0 = lrow[mt][0], l1 = lrow[mt][1];
        l0 += __shfl_xor_sync(0xffffffffu, l0, 1);
        l0 += __shfl_xor_sync(0xffffffffu, l0, 2);
        l1 += __shfl_xor_sync(0xffffffffu, l1, 1);
        l1 += __shfl_xor_sync(0xffffffffu, l1, 2);
        float i0 = 1.f / l0, i1 = 1.f / l1;
        int grow = gi * SEQ + m0 + mt * 16 + g;
#pragma unroll
        for (int nt = 0; nt < 2; ++nt) {
            int col = h * 16 + nt * 8 + 2 * tig;
            *(float2*)(ao + (size_t)grow * DD + col) =
                make_float2(o[mt][nt][0] * i0, o[mt][nt][1] * i0);
            *(float2*)(ao + (size_t)(grow + 8) * DD + col) =
                make_float2(o[mt][nt][2] * i1, o[mt][nt][3] * i1);
        }
    }
}

// =====================================================================
// BatchNorm apply (final)
// =====================================================================
__global__ void __launch_bounds__(256)
bn_apply_one(const float* __restrict__ X, const float* __restrict__ stats,
             const float* __restrict__ gamma, const float* __restrict__ beta,
             float* __restrict__ out)
{
    int col = threadIdx.x & 127;
    int half = threadIdx.x >> 7;
    float sc, sh;
    bn_coef(stats, gamma, beta, col, sc, sh);
    int row0 = blockIdx.x * 128 + half * 64;
    size_t off = (size_t)row0 * DD + col;
#pragma unroll 4
    for (int r = 0; r < 64; ++r)
        out[off + r * DD] = X[off + r * DD] * sc + sh;
}

// =====================================================================
// Host launcher — two-stream fork/join captured as a branching graph.
// =====================================================================
extern "C" void kernel_launch(void* const* d_in, const int* in_sizes, int n_in,
                              void* d_out, int out_size)
{
    const float* x          = (const float*)d_in[0];
    const int*   edge_index = (const int*)  d_in[1];
    const float* edge_attr  = (const float*)d_in[2];
    const float* gin_w1     = (const float*)d_in[3];
    const float* gin_b1     = (const float*)d_in[4];
    const float* gin_w2     = (const float*)d_in[5];
    const float* gin_b2     = (const float*)d_in[6];
    const float* bn1l_g     = (const float*)d_in[7];
    const float* bn1l_b     = (const float*)d_in[8];
    const float* in_proj_w  = (const float*)d_in[9];
    const float* in_proj_b  = (const float*)d_in[10];
    const float* out_proj_w = (const float*)d_in[11];
    const float* out_proj_b = (const float*)d_in[12];
    const float* bn1a_g     = (const float*)d_in[13];
    const float* bn1a_b     = (const float*)d_in[14];
    const float* ff_w1      = (const float*)d_in[15];
    const float* ff_b1      = (const float*)d_in[16];
    const float* ff_w2      = (const float*)d_in[17];
    const float* ff_b2      = (const float*)d_in[18];
    const float* bn2_g      = (const float*)d_in[19];
    const float* bn2_b      = (const float*)d_in[20];
    float* out = (float*)d_out;

    static cudaStream_t sB = nullptr;
    static cudaEvent_t evFork = nullptr, evJoin = nullptr;
    if (sB == nullptr) {
        cudaStreamCreateWithFlags(&sB, cudaStreamNonBlocking);
        cudaEventCreateWithFlags(&evFork, cudaEventDisableTiming);
        cudaEventCreateWithFlags(&evJoin, cudaEventDisableTiming);
        cudaFuncSetAttribute(attn_mma, cudaFuncAttributeMaxDynamicSharedMemorySize, ATTN_SMEM);
        cudaFuncSetAttribute(gemm_qkv_bf16, cudaFuncAttributeMaxDynamicSharedMemorySize, GEMM_BF_SMEM);
        cudaFuncSetAttribute(gemm_ar<true, true>, cudaFuncAttributeMaxDynamicSharedMemorySize, GEMM_AR_SMEM);
        cudaFuncSetAttribute(mlp_fused<1, true, false>, cudaFuncAttributeMaxDynamicSharedMemorySize, MLP_SMEM);
        cudaFuncSetAttribute(mlp_fused<2, true, true >, cudaFuncAttributeMaxDynamicSharedMemorySize, MLP_SMEM);
    }

    float *z, *hl, *qkvb, *ao, *ha, *h2, *stats;
    int *deg, *off, *pos, *eid;
    cudaGetSymbolAddress((void**)&z,    g_z);
    cudaGetSymbolAddress((void**)&hl,   g_hl);
    cudaGetSymbolAddress((void**)&qkvb, g_qkv);
    cudaGetSymbolAddress((void**)&ao,   g_ao);
    cudaGetSymbolAddress((void**)&ha,   g_ha);
    cudaGetSymbolAddress((void**)&h2,   g_h2);
    cudaGetSymbolAddress((void**)&stats, g_stats);
    cudaGetSymbolAddress((void**)&deg,  g_deg);
    cudaGetSymbolAddress((void**)&off,  g_off);
    cudaGetSymbolAddress((void**)&pos,  g_pos);
    cudaGetSymbolAddress((void**)&eid,  g_eid);

    const int* src = edge_index;
    const int* dst = edge_index + EE;
    const dim3 blk(256);
    const int GB = NN / 128;

    float* stats_hl = stats;
    float* stats_ha = stats + 256;
    float* stats_h2 = stats + 512;

    // ---- common prologue on null stream ----
    zero_misc<<<64, blk>>>(deg, stats);                                            // 0

    // ---- fork: stream B = attention branch ----
    cudaEventRecord(evFork, 0);
    cudaStreamWaitEvent(sB, evFork, 0);

    gemm_qkv_bf16<<<dim3(GB, 3), blk, GEMM_BF_SMEM, sB>>>(
        x, in_proj_w, in_proj_b, qkvb, 384);                                       // 1 (B)
    count_kernel<<<EE / 256, blk>>>(dst, deg);                                     // 2 (A)
    attn_mma<<<NGR * NH * 2, blk, ATTN_SMEM, sB>>>(qkvb, ao);                      // 3 (B) <- profiled
    scan_kernel<<<1, 1024>>>(deg, off, pos);                                       // 4 (A)
    scatter_kernel<<<EE / 256, blk>>>(dst, pos, eid);                              // 5 (A)
    gemm_ar<true, true><<<dim3(GB, 1), blk, GEMM_AR_SMEM, sB>>>(
        ao, out_proj_w, out_proj_b, x, ha, 128, stats_ha);                         // 6 (B)
    aggr_kernel<<<NN / 8, blk>>>(x, src, edge_attr, off, eid, z);                  // 7 (A)
    mlp_fused<1, true, false><<<GB, blk, MLP_SMEM>>>(
        z, gin_w1, gin_b1, gin_w2, gin_b2, x, hl, stats_hl,
        nullptr, nullptr, nullptr, nullptr, nullptr, nullptr);                     // 8 (A)

    // ---- join ----
    cudaEventRecord(evJoin, sB);
    cudaStreamWaitEvent(0, evJoin, 0);

    // FFN with fused bn_dual input: A' = bn1a(ha) + bn1l(hl)
    mlp_fused<2, true, true><<<GB, blk, MLP_SMEM>>>(
        ha, ff_w1, ff_b1, ff_w2, ff_b2, hl, h2, stats_h2,
        stats_ha, bn1a_g, bn1a_b, stats_hl, bn1l_g, bn1l_b);                       // 9
    bn_apply_one<<<128, blk>>>(h2, stats_h2, bn2_g, bn2_b, out);                   // 10
}

// round 16
// speedup vs baseline: 1.1177x; 1.0017x over previous
#include <cuda_runtime.h>
#include <cuda_bf16.h>
#include <math.h>
#include <stdint.h>

// Problem constants
constexpr int NN  = 16384;   // nodes
constexpr int DD  = 128;     // dim
constexpr int EE  = 262144;  // edges
constexpr int SEQ = 512;     // nodes per graph
constexpr int NGR = 32;      // graphs
constexpr int NH  = 8;       // heads (dh = 16)

// ---------------- scratch ----------------
__device__ float g_z   [NN * DD];
__device__ float g_hl  [NN * DD];
__device__ float g_qkv [NN * 3 * DD];
__device__ float g_ao  [NN * DD];
__device__ float g_ha  [NN * DD];
__device__ float g_h2  [NN * DD];
__device__ float g_stats[768];
__device__ int   g_deg [NN];
__device__ int   g_off [NN + 1];
__device__ int   g_pos [NN];
__device__ int   g_eid [EE];

// =====================================================================
__global__ void zero_misc(int* deg, float* stats)
{
    int i = blockIdx.x * 256 + threadIdx.x;
    deg[i] = 0;
    if (i < 768) stats[i] = 0.f;
}

// =====================================================================
// CSR build by dst:  count -> scan -> scatter
// =====================================================================
__global__ void count_kernel(const int* __restrict__ dst, int* __restrict__ deg)
{
    int e = blockIdx.x * 256 + threadIdx.x;
    atomicAdd(&deg[dst[e]], 1);
}

__global__ void __launch_bounds__(1024)
scan_kernel(const int* __restrict__ deg, int* __restrict__ off, int* __restrict__ pos)
{
    __shared__ int buf[2][1024];
    int t = threadIdx.x;
    int base = t * 16;
    int loc[16];
    int sum = 0;
#pragma unroll
    for (int i = 0; i < 16; ++i) { loc[i] = sum; sum += deg[base + i]; }
    buf[0][t] = sum;
    __syncthreads();
    int sel = 0;
    for (int d = 1; d < 1024; d <<= 1) {
        int v = buf[sel][t] + (t >= d ? buf[sel][t - d] : 0);
        buf[sel ^ 1][t] = v;
        sel ^= 1;
        __syncthreads();
    }
    int excl = buf[sel][t] - sum;
#pragma unroll
    for (int i = 0; i < 16; ++i) {
        int o = excl + loc[i];
        off[base + i] = o;
        pos[base + i] = o;
    }
    if (t == 1023) off[NN] = excl + sum;
}

__global__ void scatter_kernel(const int* __restrict__ dst, int* __restrict__ pos,
                               int* __restrict__ eid)
{
    int e = blockIdx.x * 256 + threadIdx.x;
    int p = atomicAdd(&pos[dst[e]], 1);
    eid[p] = e;
}

// =====================================================================
// Gather aggregation: z = x + sum_{e -> node} relu(x[src[e]] + ea[e])
// =====================================================================
__global__ void __launch_bounds__(256)
aggr_kernel(const float* __restrict__ x, const int* __restrict__ src,
            const float* __restrict__ ea, const int* __restrict__ off,
            const int* __restrict__ eid, float* __restrict__ z)
{
    int node = blockIdx.x * 8 + (threadIdx.x >> 5);
    int lane = threadIdx.x & 31;
    int beg = off[node], end = off[node + 1];
    const float4* x4  = (const float4*)x;
    const float4* ea4 = (const float4*)ea;
    float4 acc = make_float4(0.f, 0.f, 0.f, 0.f);
#pragma unroll 2
    for (int i = beg; i < end; ++i) {
        int e = __ldg(eid + i);
        int s = __ldg(src + e);
        float4 a = x4[(size_t)s * 32 + lane];
        float4 b = ea4[(size_t)e * 32 + lane];
        acc.x += fmaxf(a.x + b.x, 0.f);
        acc.y += fmaxf(a.y + b.y, 0.f);
        acc.z += fmaxf(a.z + b.z, 0.f);
        acc.w += fmaxf(a.w + b.w, 0.f);
    }
    float4 xv = x4[(size_t)node * 32 + lane];
    ((float4*)z)[(size_t)node * 32 + lane] =
        make_float4(xv.x + acc.x, xv.y + acc.y, xv.z + acc.z, xv.w + acc.w);
}

// =====================================================================
// mma helpers
// =====================================================================
__device__ __forceinline__ uint32_t to_tf32(float f)
{
    uint32_t u;
    asm("cvt.rna.tf32.f32 %0, %1;" : "=r"(u) : "f"(f));
    return u;
}

__device__ __forceinline__ void mma_tf32(float c[4], const uint32_t a[4], const uint32_t b[2])
{
    asm volatile(
        "mma.sync.aligned.m16n8k8.row.col.f32.tf32.tf32.f32 "
        "{%0,%1,%2,%3}, {%4,%5,%6,%7}, {%8,%9}, {%0,%1,%2,%3};\n"
        : "+f"(c[0]), "+f"(c[1]), "+f"(c[2]), "+f"(c[3])
        : "r"(a[0]), "r"(a[1]), "r"(a[2]), "r"(a[3]), "r"(b[0]), "r"(b[1]));
}

__device__ __forceinline__ void mma_bf16(float c[4], const uint32_t a[4], const uint32_t b[2])
{
    asm volatile(
        "mma.sync.aligned.m16n8k16.row.col.f32.bf16.bf16.f32 "
        "{%0,%1,%2,%3}, {%4,%5,%6,%7}, {%8,%9}, {%0,%1,%2,%3};\n"
        : "+f"(c[0]), "+f"(c[1]), "+f"(c[2]), "+f"(c[3])
        : "r"(a[0]), "r"(a[1]), "r"(a[2]), "r"(a[3]), "r"(b[0]), "r"(b[1]));
}

__device__ __forceinline__ uint32_t packbf(float lo, float hi)
{
    uint32_t r;
    asm("cvt.rn.bf16x2.f32 %0, %1, %2;" : "=r"(r) : "f"(hi), "f"(lo));
    return r;
}

__device__ __forceinline__ float fex2(float x)
{
    float y;
    asm("ex2.approx.f32 %0, %1;" : "=f"(y) : "f"(x));
    return y;
}

constexpr int AST  = 132;   // A/T smem stride (u32, tf32)
constexpr int BST  = 20;    // [n][k] B-chunk stride (gemm_ar tf32)
constexpr int BSTK = 132;   // [k][n] B-chunk stride (mlp_fused)
constexpr int ABH  = 68;    // A stride for bf16-pair layout (4g+tig conflict-free)
constexpr int BBH  = 12;    // B stride for bf16-pair layout (12g+tig conflict-free)

// one 16-k-slab: A-src (stride AST), B-chunk [n][k] (stride BST)
__device__ __forceinline__ void mma_slab16(const uint32_t* S, const uint32_t* Bb,
                                           float acc[4][4][4],
                                           int wm, int wn, int g, int tig, int kt)
{
#pragma unroll
    for (int k8s = 0; k8s < 2; ++k8s) {
        const int kk = kt * 16 + k8s * 8;
        uint32_t af[4][4];
#pragma unroll
        for (int mf = 0; mf < 4; ++mf) {
            const uint32_t* pa = S + (wm * 64 + mf * 16 + g) * AST + kk + tig;
            af[mf][0] = pa[0];
            af[mf][1] = pa[8 * AST];
            af[mf][2] = pa[4];
            af[mf][3] = pa[8 * AST + 4];
        }
        uint32_t bf[4][2];
#pragma unroll
        for (int nf = 0; nf < 4; ++nf) {
            const uint32_t* pb = Bb + (wn * 32 + nf * 8 + g) * BST + k8s * 8 + tig;
            bf[nf][0] = pb[0];
            bf[nf][1] = pb[4];
        }
#pragma unroll
        for (int mf = 0; mf < 4; ++mf)
#pragma unroll
            for (int nf = 0; nf < 4; ++nf)
                mma_tf32(acc[mf][nf], af[mf], bf[nf]);
    }
}

// one 16-k-slab: A-src (stride AST), B-chunk [k][n] (stride BSTK; 16 rows)
__device__ __forceinline__ void mma_slab16_kn(const uint32_t* S, const uint32_t* Bkn,
                                              float acc[4][4][4],
                                              int wm, int wn, int g, int tig, int kt)
{
#pragma unroll
    for (int k8s = 0; k8s < 2; ++k8s) {
        const int kk = kt * 16 + k8s * 8;
        uint32_t af[4][4];
#pragma unroll
        for (int mf = 0; mf < 4; ++mf) {
            const uint32_t* pa = S + (wm * 64 + mf * 16 + g) * AST + kk + tig;
            af[mf][0] = pa[0];
            af[mf][1] = pa[8 * AST];
            af[mf][2] = pa[4];
            af[mf][3] = pa[8 * AST + 4];
        }
        uint32_t bf[4][2];
        const uint32_t* pb0 = Bkn + (k8s * 8 + tig) * BSTK;
        const uint32_t* pb1 = pb0 + 4 * BSTK;
#pragma unroll
        for (int nf = 0; nf < 4; ++nf) {
            int n = wn * 32 + nf * 8 + g;
            bf[nf][0] = pb0[n];
            bf[nf][1] = pb1[n];
        }
#pragma unroll
        for (int mf = 0; mf < 4; ++mf)
#pragma unroll
            for (int nf = 0; nf < 4; ++nf)
                mma_tf32(acc[mf][nf], af[mf], bf[nf]);
    }
}

// epilogue shared by all GEMM kernels (MF=4)
template<bool RELU, bool RESID, bool STATS, bool BNRES>
__device__ __forceinline__ void gemm_epilogue(
    float acc[4][4][4], const float* bias, const float* resid,
    float* C, int ldc, int m0, int n0,
    int wm, int wn, int g, int tig, int tid,
    float* stats, float* sst,
    const float* haP, const float* hlP, const float* coef)
{
    float cs[8], cq[8];
    if (STATS) {
#pragma unroll
        for (int j = 0; j < 8; ++j) { cs[j] = 0.f; cq[j] = 0.f; }
    }
#pragma unroll
    for (int mf = 0; mf < 4; ++mf) {
#pragma unroll
        for (int nf = 0; nf < 4; ++nf) {
            int row = m0 + wm * 64 + mf * 16 + g;
            int col = n0 + wn * 32 + nf * 8 + 2 * tig;
            float b0 = bias[col], b1 = bias[col + 1];
            float o00 = acc[mf][nf][0] + b0, o01 = acc[mf][nf][1] + b1;
            float o10 = acc[mf][nf][2] + b0, o11 = acc[mf][nf][3] + b1;
            if (RELU) {
                o00 = fmaxf(o00, 0.f); o01 = fmaxf(o01, 0.f);
                o10 = fmaxf(o10, 0.f); o11 = fmaxf(o11, 0.f);
            }
            if (RESID) {
                float2 r0, r1;
                if (BNRES) {
                    float sA0 = coef[col],       hA0 = coef[128 + col];
                    float sA1 = coef[col + 1],   hA1 = coef[128 + col + 1];
                    float sL0 = coef[256 + col], hL0 = coef[384 + col];
                    float sL1 = coef[256 + col + 1], hL1 = coef[384 + col + 1];
                    float2 a0 = *(const float2*)(haP + (size_t)row * ldc + col);
                    float2 a1 = *(const float2*)(haP + (size_t)(row + 8) * ldc + col);
                    float2 l0 = *(const float2*)(hlP + (size_t)row * ldc + col);
                    float2 l1 = *(const float2*)(hlP + (size_t)(row + 8) * ldc + col);
                    r0.x = a0.x * sA0 + hA0 + l0.x * sL0 + hL0;
                    r0.y = a0.y * sA1 + hA1 + l0.y * sL1 + hL1;
                    r1.x = a1.x * sA0 + hA0 + l1.x * sL0 + hL0;
                    r1.y = a1.y * sA1 + hA1 + l1.y * sL1 + hL1;
                } else {
                    r0 = *(const float2*)(resid + (size_t)row * ldc + col);
                    r1 = *(const float2*)(resid + (size_t)(row + 8) * ldc + col);
                }
                o00 += r0.x; o01 += r0.y;
                o10 += r1.x; o11 += r1.y;
            }
            if (STATS) {
                cs[nf*2]   += o00 + o10;
                cs[nf*2+1] += o01 + o11;
                cq[nf*2]   += o00*o00 + o10*o10;
                cq[nf*2+1] += o01*o01 + o11*o11;
            }
            *(float2*)(C + (size_t)row * ldc + col)       = make_float2(o00, o01);
            *(float2*)(C + (size_t)(row + 8) * ldc + col) = make_float2(o10, o11);
        }
    }
    if (STATS) {
        __syncthreads();
        sst[tid] = 0.f;
        __syncthreads();
#pragma unroll
        for (int j = 0; j < 8; ++j) {
            int col = wn * 32 + (j >> 1) * 8 + 2 * tig + (j & 1);
            atomicAdd(&sst[col],       cs[j]);
            atomicAdd(&sst[128 + col], cq[j]);
        }
        __syncthreads();
        atomicAdd(&stats[tid], sst[tid]);
    }
}

// BN coefficient helper
__device__ __forceinline__ void bn_coef(const float* stats, const float* gamma,
                                        const float* beta, int col,
                                        float& sc, float& sh)
{
    float mean = stats[col] * (1.f / (float)NN);
    float var  = stats[128 + col] * (1.f / (float)NN) - mean * mean;
    sc = gamma[col] * rsqrtf(var + 1e-5f);
    sh = beta[col] - mean * sc;
}

// =====================================================================
// BF16 A-resident GEMM (K=128) — used for QKV only (feeds bf16 attention).
// C = A @ B^T + bias. A packed bf16x2 pairs [128][ABH]; B chunks [n][BBH].
// Double-buffered, one sync per k-chunk. 128 bf16 mma per block.
// =====================================================================
constexpr int GEMM_BF_SMEM = (128 * ABH + 2 * 128 * BBH) * 4;   // ~47KB

__global__ void __launch_bounds__(256, 2)
gemm_qkv_bf16(const float* __restrict__ A,
              const float* __restrict__ B,
              const float* __restrict__ bias,
              float* __restrict__ C, int ldc)
{
    extern __shared__ uint32_t sm[];
    uint32_t* Abuf = sm;                 // [128][ABH] bf16x2 pairs
    uint32_t* Bb0  = sm + 128 * ABH;     // [128][BBH] stage 0
    uint32_t* Bb1  = Bb0 + 128 * BBH;    // stage 1

    const int tid = threadIdx.x;
    const int lane = tid & 31, warp = tid >> 5;
    const int wm = warp >> 2, wn = warp & 3;
    const int g = lane >> 2, tig = lane & 3;
    const int m0 = blockIdx.x * 128;
    const int n0 = blockIdx.y * 128;
    const int i0 = tid, i1 = tid + 256;
    const float* Bp0 = B + (size_t)(n0 + (i0 >> 2)) * 128 + (i0 & 3) * 4;
    const float* Bp1 = B + (size_t)(n0 + (i1 >> 2)) * 128 + (i1 & 3) * 4;
    const int o0 = (i0 >> 2) * BBH + (i0 & 3) * 2;   // pair offsets
    const int o1 = (i1 >> 2) * BBH + (i1 & 3) * 2;

    // stage A (pack pairs along k)
#pragma unroll
    for (int it = 0; it < 16; ++it) {
        int idx = tid + it * 256;
        int r = idx >> 5, c4 = (idx & 31) * 4;
        float4 v = *(const float4*)(A + (size_t)(m0 + r) * 128 + c4);
        uint32_t* d = Abuf + r * ABH + (c4 >> 1);
        d[0] = packbf(v.x, v.y);
        d[1] = packbf(v.z, v.w);
    }

    float acc[4][4][4];
#pragma unroll
    for (int i = 0; i < 4; ++i)
#pragma unroll
        for (int j = 0; j < 4; ++j)
#pragma unroll
            for (int r = 0; r < 4; ++r) acc[i][j][r] = 0.f;

    // chunk 0 -> stage 0, prefetch chunk 1
    float4 pre0 = *(const float4*)(Bp0);
    float4 pre1 = *(const float4*)(Bp1);
    {
        uint32_t* d0 = Bb0 + o0;
        d0[0] = packbf(pre0.x, pre0.y); d0[1] = packbf(pre0.z, pre0.w);
        uint32_t* d1 = Bb0 + o1;
        d1[0] = packbf(pre1.x, pre1.y); d1[1] = packbf(pre1.z, pre1.w);
    }
    pre0 = *(const float4*)(Bp0 + 16);
    pre1 = *(const float4*)(Bp1 + 16);
    __syncthreads();

    for (int kt = 0; kt < 8; ++kt) {
        if (kt < 7) {
            uint32_t* stg = (kt & 1) ? Bb0 : Bb1;
            uint32_t* d0 = stg + o0;
            d0[0] = packbf(pre0.x, pre0.y); d0[1] = packbf(pre0.z, pre0.w);
            uint32_t* d1 = stg + o1;
            d1[0] = packbf(pre1.x, pre1.y); d1[1] = packbf(pre1.z, pre1.w);
            if (kt < 6) {
                pre0 = *(const float4*)(Bp0 + (kt + 2) * 16);
                pre1 = *(const float4*)(Bp1 + (kt + 2) * 16);
            }
        }
        // mma: one k16 slab (bf16)
        {
            const uint32_t* Bb = (kt & 1) ? Bb1 : Bb0;
            uint32_t af[4][4];
#pragma unroll
            for (int mf = 0; mf < 4; ++mf) {
                const uint32_t* pa = Abuf + (wm * 64 + mf * 16 + g) * ABH + kt * 8 + tig;
                af[mf][0] = pa[0];
                af[mf][1] = pa[8 * ABH];
                af[mf][2] = pa[4];
                af[mf][3] = pa[8 * ABH + 4];
            }
            uint32_t bf[4][2];
#pragma unroll
            for (int nf = 0; nf < 4; ++nf) {
                const uint32_t* pb = Bb + (wn * 32 + nf * 8 + g) * BBH + tig;
                bf[nf][0] = pb[0];
                bf[nf][1] = pb[4];
            }
#pragma unroll
            for (int mf = 0; mf < 4; ++mf)
#pragma unroll
                for (int nf = 0; nf < 4; ++nf)
                    mma_bf16(acc[mf][nf], af[mf], bf[nf]);
        }
        if (kt < 7) __syncthreads();
    }

    // epilogue: bias + store
#pragma unroll
    for (int mf = 0; mf < 4; ++mf) {
#pragma unroll
        for (int nf = 0; nf < 4; ++nf) {
            int row = m0 + wm * 64 + mf * 16 + g;
            int col = n0 + wn * 32 + nf * 8 + 2 * tig;
            float b0 = bias[col], b1 = bias[col + 1];
            *(float2*)(C + (size_t)row * ldc + col) =
                make_float2(acc[mf][nf][0] + b0, acc[mf][nf][1] + b1);
            *(float2*)(C + (size_t)(row + 8) * ldc + col) =
                make_float2(acc[mf][nf][2] + b0, acc[mf][nf][3] + b1);
        }
    }
}

// =====================================================================
// A-resident TF32 GEMM (K=128): used for out_proj (precision-sensitive).
// =====================================================================
constexpr int GEMM_AR_SMEM = (128 * AST + 2 * 128 * BST) * 4;

template<bool RESID, bool STATS>
__global__ void __launch_bounds__(256, 2)
gemm_ar(const float* __restrict__ A,
        const float* __restrict__ B,
        const float* __restrict__ bias,
        const float* __restrict__ resid,
        float* __restrict__ C, int ldc,
        float* __restrict__ stats)
{
    extern __shared__ uint32_t sm[];
    uint32_t* Abuf = sm;
    uint32_t* Bb0  = sm + 128 * AST;
    uint32_t* Bb1  = Bb0 + 128 * BST;

    const int tid = threadIdx.x;
    const int lane = tid & 31, warp = tid >> 5;
    const int wm = warp >> 2, wn = warp & 3;
    const int g = lane >> 2, tig = lane & 3;
    const int m0 = blockIdx.x * 128;
    const int n0 = blockIdx.y * 128;
    const int i0 = tid, i1 = tid + 256;
    const float* Bp0 = B + (size_t)(n0 + (i0 >> 2)) * 128 + (i0 & 3) * 4;
    const float* Bp1 = B + (size_t)(n0 + (i1 >> 2)) * 128 + (i1 & 3) * 4;
    const int o0 = (i0 >> 2) * BST + (i0 & 3) * 4;
    const int o1 = (i1 >> 2) * BST + (i1 & 3) * 4;

#pragma unroll
    for (int it = 0; it < 16; ++it) {
        int idx = tid + it * 256;
        int r = idx >> 5, c4 = (idx & 31) * 4;
        float4 v = *(const float4*)(A + (size_t)(m0 + r) * 128 + c4);
        uint32_t* d = Abuf + r * AST + c4;
        d[0] = to_tf32(v.x); d[1] = to_tf32(v.y);
        d[2] = to_tf32(v.z); d[3] = to_tf32(v.w);
    }

    float acc[4][4][4];
#pragma unroll
    for (int i = 0; i < 4; ++i)
#pragma unroll
        for (int j = 0; j < 4; ++j)
#pragma unroll
            for (int r = 0; r < 4; ++r) acc[i][j][r] = 0.f;

    float4 pre0 = *(const float4*)(Bp0);
    float4 pre1 = *(const float4*)(Bp1);
    {
        uint32_t* d0 = Bb0 + o0;
        d0[0] = to_tf32(pre0.x); d0[1] = to_tf32(pre0.y);
        d0[2] = to_tf32(pre0.z); d0[3] = to_tf32(pre0.w);
        uint32_t* d1 = Bb0 + o1;
        d1[0] = to_tf32(pre1.x); d1[1] = to_tf32(pre1.y);
        d1[2] = to_tf32(pre1.z); d1[3] = to_tf32(pre1.w);
    }
    pre0 = *(const float4*)(Bp0 + 16);
    pre1 = *(const float4*)(Bp1 + 16);
    __syncthreads();

    for (int kt = 0; kt < 8; ++kt) {
        if (kt < 7) {
            uint32_t* stg = (kt & 1) ? Bb0 : Bb1;
            uint32_t* d0 = stg + o0;
            d0[0] = to_tf32(pre0.x); d0[1] = to_tf32(pre0.y);
            d0[2] = to_tf32(pre0.z); d0[3] = to_tf32(pre0.w);
            uint32_t* d1 = stg + o1;
            d1[0] = to_tf32(pre1.x); d1[1] = to_tf32(pre1.y);
            d1[2] = to_tf32(pre1.z); d1[3] = to_tf32(pre1.w);
            if (kt < 6) {
                pre0 = *(const float4*)(Bp0 + (kt + 2) * 16);
                pre1 = *(const float4*)(Bp1 + (kt + 2) * 16);
            }
        }
        mma_slab16(Abuf, (kt & 1) ? Bb1 : Bb0, acc, wm, wn, g, tig, kt);
        if (kt < 7) __syncthreads();
    }

    gemm_epilogue<false, RESID, STATS, false>(acc, bias, resid, C, ldc, m0, n0,
                                              wm, wn, g, tig, tid, stats, (float*)Bb0,
                                              nullptr, nullptr, nullptr);
}

// =====================================================================
// Fused MLP: C = relu(A' @ W1 + b1) @ W2 + b2 + resid' (+stats)
// BNIN: A' = bnA(A=ha) + bnL(resid=hl) inline; residual recomputed in epilogue.
// =====================================================================
constexpr int MLP_SMEM = (2 * 128 * AST + 2 * 16 * BSTK) * 4;   // ~152KB

template<int NC, bool STATS, bool BNIN>
__global__ void __launch_bounds__(256, 1)
mlp_fused(const float* __restrict__ A,
          const float* __restrict__ W1, const float* __restrict__ b1,
          const float* __restrict__ W2, const float* __restrict__ b2,
          const float* __restrict__ resid,
          float* __restrict__ C,
          float* __restrict__ stats,
          const float* __restrict__ stA, const float* __restrict__ gA,
          const float* __restrict__ bA,
          const float* __restrict__ stL, const float* __restrict__ gL,
          const float* __restrict__ bL)
{
    extern __shared__ uint32_t sm[];
    uint32_t* Abuf = sm;                   // [128][AST]
    uint32_t* Tbuf = sm + 128 * AST;       // [128][AST]
    uint32_t* Bb0  = sm + 2 * 128 * AST;   // [16][BSTK] stage 0
    uint32_t* Bb1  = Bb0 + 16 * BSTK;      // [16][BSTK] stage 1
    __shared__ float coef[512];

    const int tid = threadIdx.x;
    const int lane = tid & 31, warp = tid >> 5;
    const int wm = warp >> 2, wn = warp & 3;
    const int g = lane >> 2, tig = lane & 3;
    const int m0 = blockIdx.x * 128;
    const int ldw1 = NC * 128;

    const int i0 = tid, i1 = tid + 256;
    const int k0 = i0 >> 5, c40 = (i0 & 31) * 4;
    const int k1 = i1 >> 5, c41 = (i1 & 31) * 4;
    const int o0 = k0 * BSTK + c40;
    const int o1 = k1 * BSTK + c41;

    if (BNIN) {
        if (tid < 128) {
            float sc, sh;
            bn_coef(stA, gA, bA, tid, sc, sh);
            coef[tid] = sc; coef[128 + tid] = sh;
            bn_coef(stL, gL, bL, tid, sc, sh);
            coef[256 + tid] = sc; coef[384 + tid] = sh;
        }
        __syncthreads();
    }

#pragma unroll
    for (int it = 0; it < 16; ++it) {
        int idx = tid + it * 256;
        int r = idx >> 5, c4 = (idx & 31) * 4;
        float4 v = *(const float4*)(A + (size_t)(m0 + r) * 128 + c4);
        if (BNIN) {
            float4 w = *(const float4*)(resid + (size_t)(m0 + r) * 128 + c4);
            v.x = v.x * coef[c4]     + coef[128 + c4]     + w.x * coef[256 + c4]     + coef[384 + c4];
            v.y = v.y * coef[c4 + 1] + coef[128 + c4 + 1] + w.y * coef[256 + c4 + 1] + coef[384 + c4 + 1];
            v.z = v.z * coef[c4 + 2] + coef[128 + c4 + 2] + w.z * coef[256 + c4 + 2] + coef[384 + c4 + 2];
            v.w = v.w * coef[c4 + 3] + coef[128 + c4 + 3] + w.w * coef[256 + c4 + 3] + coef[384 + c4 + 3];
        }
        uint32_t* d = Abuf + r * AST + c4;
        d[0] = to_tf32(v.x); d[1] = to_tf32(v.y);
        d[2] = to_tf32(v.z); d[3] = to_tf32(v.w);
    }

    float co[4][4][4];
#pragma unroll
    for (int i = 0; i < 4; ++i)
#pragma unroll
        for (int j = 0; j < 4; ++j)
#pragma unroll
            for (int r = 0; r < 4; ++r) co[i][j][r] = 0.f;

#pragma unroll
    for (int nc = 0; nc < NC; ++nc) {
        // ============ phase 1: c1 = A' @ W1[:, nc*128..] ============
        float c1[4][4][4];
#pragma unroll
        for (int i = 0; i < 4; ++i)
#pragma unroll
            for (int j = 0; j < 4; ++j)
#pragma unroll
                for (int r = 0; r < 4; ++r) c1[i][j][r] = 0.f;

        const float* Wp = W1 + nc * 128;
        float4 pre0 = *(const float4*)(Wp + (size_t)k0 * ldw1 + c40);
        float4 pre1 = *(const float4*)(Wp + (size_t)k1 * ldw1 + c41);
        if (nc) __syncthreads();
        {
            uint32_t* d0 = Bb0 + o0;
            d0[0] = to_tf32(pre0.x); d0[1] = to_tf32(pre0.y);
            d0[2] = to_tf32(pre0.z); d0[3] = to_tf32(pre0.w);
            uint32_t* d1 = Bb0 + o1;
            d1[0] = to_tf32(pre1.x); d1[1] = to_tf32(pre1.y);
            d1[2] = to_tf32(pre1.z); d1[3] = to_tf32(pre1.w);
        }
        pre0 = *(const float4*)(Wp + (size_t)(16 + k0) * ldw1 + c40);
        pre1 = *(const float4*)(Wp + (size_t)(16 + k1) * ldw1 + c41);
        __syncthreads();

        for (int kt = 0; kt < 8; ++kt) {
            if (kt < 7) {
                uint32_t* stg = (kt & 1) ? Bb0 : Bb1;
                uint32_t* d0 = stg + o0;
                d0[0] = to_tf32(pre0.x); d0[1] = to_tf32(pre0.y);
                d0[2] = to_tf32(pre0.z); d0[3] = to_tf32(pre0.w);
                uint32_t* d1 = stg + o1;
                d1[0] = to_tf32(pre1.x); d1[1] = to_tf32(pre1.y);
                d1[2] = to_tf32(pre1.z); d1[3] = to_tf32(pre1.w);
                if (kt < 6) {
                    pre0 = *(const float4*)(Wp + (size_t)((kt + 2) * 16 + k0) * ldw1 + c40);
                    pre1 = *(const float4*)(Wp + (size_t)((kt + 2) * 16 + k1) * ldw1 + c41);
                }
            }
            mma_slab16_kn(Abuf, (kt & 1) ? Bb1 : Bb0, c1, wm, wn, g, tig, kt);
            if (kt < 7) __syncthreads();
        }

        // write hidden tile: relu(c1 + b1chunk) -> Tbuf (tf32)
#pragma unroll
        for (int mf = 0; mf < 4; ++mf) {
#pragma unroll
            for (int nf = 0; nf < 4; ++nf) {
                int row = wm * 64 + mf * 16 + g;
                int col = wn * 32 + nf * 8 + 2 * tig;
                float bb0 = b1[nc * 128 + col], bb1 = b1[nc * 128 + col + 1];
                Tbuf[row * AST + col]           = to_tf32(fmaxf(c1[mf][nf][0] + bb0, 0.f));
                Tbuf[row * AST + col + 1]       = to_tf32(fmaxf(c1[mf][nf][1] + bb1, 0.f));
                Tbuf[(row + 8) * AST + col]     = to_tf32(fmaxf(c1[mf][nf][2] + bb0, 0.f));
                Tbuf[(row + 8) * AST + col + 1] = to_tf32(fmaxf(c1[mf][nf][3] + bb1, 0.f));
            }
        }

        // ============ phase 2: co += T @ W2[nc*128.., :] ============
        const float* W2p = W2 + (size_t)(nc * 128) * 128;
        pre0 = *(const float4*)(W2p + (size_t)k0 * 128 + c40);
        pre1 = *(const float4*)(W2p + (size_t)k1 * 128 + c41);
        __syncthreads();
        {
            uint32_t* d0 = Bb0 + o0;
            d0[0] = to_tf32(pre0.x); d0[1] = to_tf32(pre0.y);
            d0[2] = to_tf32(pre0.z); d0[3] = to_tf32(pre0.w);
            uint32_t* d1 = Bb0 + o1;
            d1[0] = to_tf32(pre1.x); d1[1] = to_tf32(pre1.y);
            d1[2] = to_tf32(pre1.z); d1[3] = to_tf32(pre1.w);
        }
        pre0 = *(const float4*)(W2p + (size_t)(16 + k0) * 128 + c40);
        pre1 = *(const float4*)(W2p + (size_t)(16 + k1) * 128 + c41);
        __syncthreads();

        for (int kt = 0; kt < 8; ++kt) {
            if (kt < 7) {
                uint32_t* stg = (kt & 1) ? Bb0 : Bb1;
                uint32_t* d0 = stg + o0;
                d0[0] = to_tf32(pre0.x); d0[1] = to_tf32(pre0.y);
                d0[2] = to_tf32(pre0.z); d0[3] = to_tf32(pre0.w);
                uint32_t* d1 = stg + o1;
                d1[0] = to_tf32(pre1.x); d1[1] = to_tf32(pre1.y);
                d1[2] = to_tf32(pre1.z); d1[3] = to_tf32(pre1.w);
                if (kt < 6) {
                    pre0 = *(const float4*)(W2p + (size_t)((kt + 2) * 16 + k0) * 128 + c40);
                    pre1 = *(const float4*)(W2p + (size_t)((kt + 2) * 16 + k1) * 128 + c41);
                }
            }
            mma_slab16_kn(Tbuf, (kt & 1) ? Bb1 : Bb0, co, wm, wn, g, tig, kt);
            if (kt < 7) __syncthreads();
        }
    }

    gemm_epilogue<false, true, STATS, BNIN>(co, b2, resid, C, 128, m0, 0,
                                            wm, wn, g, tig, tid, stats, (float*)Bb0,
                                            A, resid, coef);
}

// =====================================================================
// Flash-style BF16 attention v4: exp2-domain scores, occupancy 3.
// =====================================================================
constexpr int KP_ST = 12;
constexpr int VP_ST = 24;
constexpr int ATTN_SMEM = (512 * KP_ST + 256 * VP_ST) * 4;   // 48KB

__global__ void __launch_bounds__(256, 3)
attn_mma(const float* __restrict__ qkv, float* __restrict__ ao)
{
    extern __shared__ uint32_t sm[];
    uint32_t* Ksp = sm;
    uint32_t* Vsp = sm + 512 * KP_ST;

    const int tid  = threadIdx.x;
    const int lane = tid & 31;
    const int warp = tid >> 5;
    const int g    = lane >> 2;
    const int tig  = lane & 3;
    const int b    = blockIdx.x;
    const int gi = b >> 4, h = (b >> 1) & 7, half = b & 1;
    const float* base = qkv + (size_t)gi * SEQ * 384;
    const int m0 = half * 256 + warp * 32;
    const float QSC = 0.25f * 1.44269504f;

    for (int idx = tid; idx < 2048; idx += 256) {
        int r = idx >> 2, c4 = (idx & 3) * 4;
        float4 kv = *(const float4*)(base + (size_t)r * 384 + 128 + h * 16 + c4);
        Ksp[r * KP_ST + (c4 >> 1)]     = packbf(kv.x, kv.y);
        Ksp[r * KP_ST + (c4 >> 1) + 1] = packbf(kv.z, kv.w);
        if (idx < 1024) {
            int pr = r, dg = c4;
            float4 v0 = *(const float4*)(base + (size_t)(2 * pr)     * 384 + 256 + h * 16 + dg);
            float4 v1 = *(const float4*)(base + (size_t)(2 * pr + 1) * 384 + 256 + h * 16 + dg);
            uint32_t* vd = Vsp + pr * VP_ST + dg;
            vd[0] = packbf(v0.x, v1.x);
            vd[1] = packbf(v0.y, v1.y);
            vd[2] = packbf(v0.z, v1.z);
            vd[3] = packbf(v0.w, v1.w);
        }
    }

    uint32_t qa[2][4];
#pragma unroll
    for (int mt = 0; mt < 2; ++mt) {
        const float* qp = base + (size_t)(m0 + mt * 16 + g) * 384 + h * 16;
        float2 a0 = *(const float2*)(qp + 2 * tig);
        float2 a1 = *(const float2*)(qp + 8 * 384 + 2 * tig);
        float2 a2 = *(const float2*)(qp + 2 * tig + 8);
        float2 a3 = *(const float2*)(qp + 8 * 384 + 2 * tig + 8);
        qa[mt][0] = packbf(a0.x * QSC, a0.y * QSC);
        qa[mt][1] = packbf(a1.x * QSC, a1.y * QSC);
        qa[mt][2] = packbf(a2.x * QSC, a2.y * QSC);
        qa[mt][3] = packbf(a3.x * QSC, a3.y * QSC);
    }
    __syncthreads();

    float o[2][2][4];
    float lrow[2][2];
#pragma unroll
    for (int mt = 0; mt < 2; ++mt) {
        lrow[mt][0] = 0.f; lrow[mt][1] = 0.f;
#pragma unroll
        for (int nt = 0; nt < 2; ++nt)
#pragma unroll
            for (int r = 0; r < 4; ++r) o[mt][nt][r] = 0.f;
    }

    for (int j = 0; j < 16; ++j) {
        const int n0 = j * 32;
        uint32_t ps[2][2][4];

#pragma unroll
        for (int nt = 0; nt < 4; ++nt) {
            uint32_t bk[2];
            {
                const uint32_t* kp = Ksp + (n0 + nt * 8 + g) * KP_ST + tig;
                bk[0] = kp[0];
                bk[1] = kp[4];
            }
#pragma unroll
            for (int mt = 0; mt < 2; ++mt) {
                float c[4] = {0.f, 0.f, 0.f, 0.f};
                mma_bf16(c, qa[mt], bk);
                float p0 = fex2(c[0]);
                float p1 = fex2(c[1]);
                float p2 = fex2(c[2]);
                float p3 = fex2(c[3]);
                lrow[mt][0] += p0 + p1;
                lrow[mt][1] += p2 + p3;
                ps[mt][nt >> 1][(nt & 1) * 2 + 0] = packbf(p0, p1);
                ps[mt][nt >> 1][(nt & 1) * 2 + 1] = packbf(p2, p3);
            }
        }

#pragma unroll
        for (int c = 0; c < 2; ++c) {
            const int prb = (n0 >> 1) + c * 8;
#pragma unroll
            for (int nt = 0; nt < 2; ++nt) {
                uint32_t bv[2];
                const uint32_t* vp = Vsp + (prb + tig) * VP_ST + nt * 8 + g;
                bv[0] = vp[0];
                bv[1] = vp[4 * VP_ST];
#pragma unroll
                for (int mt = 0; mt < 2; ++mt)
                    mma_bf16(o[mt][nt], ps[mt][c], bv);
            }
        }
    }

#pragma unroll
    for (int mt = 0; mt < 2; ++mt) {
        float l0 = lrow[mt][0], l1 = lrow[mt][1];
        l0 += __shfl_xor_sync(0xffffffffu, l0, 1);
        l0 += __shfl_xor_sync(0xffffffffu, l0, 2);
        l1 += __shfl_xor_sync(0xffffffffu, l1, 1);
        l1 += __shfl_xor_sync(0xffffffffu, l1, 2);
        float i0 = 1.f / l0, i1 = 1.f / l1;
        int grow = gi * SEQ + m0 + mt * 16 + g;
#pragma unroll
        for (int nt = 0; nt < 2; ++nt) {
            int col = h * 16 + nt * 8 + 2 * tig;
            *(float2*)(ao + (size_t)grow * DD + col) =
                make_float2(o[mt][nt][0] * i0, o[mt][nt][1] * i0);
            *(float2*)(ao + (size_t)(grow + 8) * DD + col) =
                make_float2(o[mt][nt][2] * i1, o[mt][nt][3] * i1);
        }
    }
}

// =====================================================================
// BatchNorm apply (final)
// =====================================================================
__global__ void __launch_bounds__(256)
bn_apply_one(const float* __restrict__ X, const float* __restrict__ stats,
             const float* __restrict__ gamma, const float* __restrict__ beta,
             float* __restrict__ out)
{
    int col = threadIdx.x & 127;
    int half = threadIdx.x >> 7;
    float sc, sh;
    bn_coef(stats, gamma, beta, col, sc, sh);
    int row0 = blockIdx.x * 128 + half * 64;
    size_t off = (size_t)row0 * DD + col;
#pragma unroll 4
    for (int r = 0; r < 64; ++r)
        out[off + r * DD] = X[off + r * DD] * sc + sh;
}

// =====================================================================
// Host launcher — two-stream fork/join captured as a branching graph.
// =====================================================================
extern "C" void kernel_launch(void* const* d_in, const int* in_sizes, int n_in,
                              void* d_out, int out_size)
{
    const float* x          = (const float*)d_in[0];
    const int*   edge_index = (const int*)  d_in[1];
    const float* edge_attr  = (const float*)d_in[2];
    const float* gin_w1     = (const float*)d_in[3];
    const float* gin_b1     = (const float*)d_in[4];
    const float* gin_w2     = (const float*)d_in[5];
    const float* gin_b2     = (const float*)d_in[6];
    const float* bn1l_g     = (const float*)d_in[7];
    const float* bn1l_b     = (const float*)d_in[8];
    const float* in_proj_w  = (const float*)d_in[9];
    const float* in_proj_b  = (const float*)d_in[10];
    const float* out_proj_w = (const float*)d_in[11];
    const float* out_proj_b = (const float*)d_in[12];
    const float* bn1a_g     = (const float*)d_in[13];
    const float* bn1a_b     = (const float*)d_in[14];
    const float* ff_w1      = (const float*)d_in[15];
    const float* ff_b1      = (const float*)d_in[16];
    const float* ff_w2      = (const float*)d_in[17];
    const float* ff_b2      = (const float*)d_in[18];
    const float* bn2_g      = (const float*)d_in[19];
    const float* bn2_b      = (const float*)d_in[20];
    float* out = (float*)d_out;

    static cudaStream_t sB = nullptr;
    static cudaEvent_t evFork = nullptr, evJoin = nullptr;
    if (sB == nullptr) {
        cudaStreamCreateWithFlags(&sB, cudaStreamNonBlocking);
        cudaEventCreateWithFlags(&evFork, cudaEventDisableTiming);
        cudaEventCreateWithFlags(&evJoin, cudaEventDisableTiming);
        cudaFuncSetAttribute(attn_mma, cudaFuncAttributeMaxDynamicSharedMemorySize, ATTN_SMEM);
        cudaFuncSetAttribute(gemm_qkv_bf16, cudaFuncAttributeMaxDynamicSharedMemorySize, GEMM_BF_SMEM);
        cudaFuncSetAttribute(gemm_ar<true, true>, cudaFuncAttributeMaxDynamicSharedMemorySize, GEMM_AR_SMEM);
        cudaFuncSetAttribute(mlp_fused<1, true, false>, cudaFuncAttributeMaxDynamicSharedMemorySize, MLP_SMEM);
        cudaFuncSetAttribute(mlp_fused<2, true, true >, cudaFuncAttributeMaxDynamicSharedMemorySize, MLP_SMEM);
    }

    float *z, *hl, *qkvb, *ao, *ha, *h2, *stats;
    int *deg, *off, *pos, *eid;
    cudaGetSymbolAddress((void**)&z,    g_z);
    cudaGetSymbolAddress((void**)&hl,   g_hl);
    cudaGetSymbolAddress((void**)&qkvb, g_qkv);
    cudaGetSymbolAddress((void**)&ao,   g_ao);
    cudaGetSymbolAddress((void**)&ha,   g_ha);
    cudaGetSymbolAddress((void**)&h2,   g_h2);
    cudaGetSymbolAddress((void**)&stats, g_stats);
    cudaGetSymbolAddress((void**)&deg,  g_deg);
    cudaGetSymbolAddress((void**)&off,  g_off);
    cudaGetSymbolAddress((void**)&pos,  g_pos);
    cudaGetSymbolAddress((void**)&eid,  g_eid);

    const int* src = edge_index;
    const int* dst = edge_index + EE;
    const dim3 blk(256);
    const int GB = NN / 128;

    float* stats_hl = stats;
    float* stats_ha = stats + 256;
    float* stats_h2 = stats + 512;

    // ---- common prologue on null stream ----
    zero_misc<<<64, blk>>>(deg, stats);                                            // 0

    // ---- fork: stream B = attention branch ----
    cudaEventRecord(evFork, 0);
    cudaStreamWaitEvent(sB, evFork, 0);

    gemm_qkv_bf16<<<dim3(GB, 3), blk, GEMM_BF_SMEM, sB>>>(
        x, in_proj_w, in_proj_b, qkvb, 384);                                       // 1 (B)
    count_kernel<<<EE / 256, blk>>>(dst, deg);                                     // 2 (A)
    attn_mma<<<NGR * NH * 2, blk, ATTN_SMEM, sB>>>(qkvb, ao);                      // 3 (B) <- profiled
    scan_kernel<<<1, 1024>>>(deg, off, pos);                                       // 4 (A)
    scatter_kernel<<<EE / 256, blk>>>(dst, pos, eid);                              // 5 (A)
    gemm_ar<true, true><<<dim3(GB, 1), blk, GEMM_AR_SMEM, sB>>>(
        ao, out_proj_w, out_proj_b, x, ha, 128, stats_ha);                         // 6 (B)
    aggr_kernel<<<NN / 8, blk>>>(x, src, edge_attr, off, eid, z);                  // 7 (A)
    mlp_fused<1, true, false><<<GB, blk, MLP_SMEM>>>(
        z, gin_w1, gin_b1, gin_w2, gin_b2, x, hl, stats_hl,
        nullptr, nullptr, nullptr, nullptr, nullptr, nullptr);                     // 8 (A)

    // ---- join ----
    cudaEventRecord(evJoin, sB);
    cudaStreamWaitEvent(0, evJoin, 0);

    // FFN with fused bn_dual input: A' = bn1a(ha) + bn1l(hl)
    mlp_fused<2, true, true><<<GB, blk, MLP_SMEM>>>(
        ha, ff_w1, ff_b1, ff_w2, ff_b2, hl, h2, stats_h2,
        stats_ha, bn1a_g, bn1a_b, stats_hl, bn1l_g, bn1l_b);                       // 9
    bn_apply_one<<<128, blk>>>(h2, stats_h2, bn2_g, bn2_b, out);                   // 10
}